// round 10
// baseline (speedup 1.0000x reference)
#include <cuda_runtime.h>
#include <cuda_bf16.h>
#include <math.h>
#include <stdint.h>

#define MROWS (4 * 8192)          // 32768 rows total
#define DIMK  512
#define NQKV  1536

// ---------------- scratch (device globals; no allocation allowed) ----------
__device__ float g_q[MROWS * 512];          // elu(q)+1 fp32
__device__ float g_k[MROWS * 512];          // elu(k)+1 fp32
__device__ float g_v[MROWS * 512];          // v fp32
__device__ float g_kvpart[32 * 16 * 4160];  // per (bh,chunk): 64x64 kv + 64 ksum
__device__ float g_kv[32 * 4160];
__device__ float g_wt[NQKV * 512];          // w_qkv^T fp32 [n][k]

__device__ __nv_bfloat16 g_xh[MROWS * 512];   // x hi/lo (same index as x)
__device__ __nv_bfloat16 g_xl[MROWS * 512];
__device__ __nv_bfloat16 g_wth[NQKV * 512];   // w^T hi/lo (same index as g_wt)
__device__ __nv_bfloat16 g_wtl[NQKV * 512];
__device__ __nv_bfloat16 g_qzh[MROWS * 512];  // (q*z) hi/lo (same index as g_q)
__device__ __nv_bfloat16 g_qzl[MROWS * 512];
__device__ __nv_bfloat16 g_wbth[4 * 512 * 512]; // Wbig^T hi/lo [b][j][r]
__device__ __nv_bfloat16 g_wbtl[4 * 512 * 512];

// ---------------- helpers ---------------------------------------------------
__device__ __forceinline__ void mma16816(float* c, const uint32_t* a, const uint32_t* b) {
    asm volatile(
        "mma.sync.aligned.m16n8k16.row.col.f32.bf16.bf16.f32 "
        "{%0,%1,%2,%3}, {%4,%5,%6,%7}, {%8,%9}, {%0,%1,%2,%3};"
        : "+f"(c[0]), "+f"(c[1]), "+f"(c[2]), "+f"(c[3])
        : "r"(a[0]), "r"(a[1]), "r"(a[2]), "r"(a[3]), "r"(b[0]), "r"(b[1]));
}
__device__ __forceinline__ void ldsm4(uint32_t* r, uint32_t a) {
    asm volatile("ldmatrix.sync.aligned.m8n8.x4.shared.b16 {%0,%1,%2,%3}, [%4];"
        : "=r"(r[0]), "=r"(r[1]), "=r"(r[2]), "=r"(r[3]) : "r"(a));
}
__device__ __forceinline__ uint32_t smem_u32(const void* p) {
    uint32_t a;
    asm("{ .reg .u64 t; cvta.to.shared.u64 t, %1; cvt.u32.u64 %0, t; }" : "=r"(a) : "l"(p));
    return a;
}
__device__ __forceinline__ void cp16(uint32_t s, const void* g) {
    asm volatile("cp.async.cg.shared.global [%0], [%1], 16;" :: "r"(s), "l"(g));
}
__device__ __forceinline__ float elu1(float x) {
    return x >= 0.f ? x + 1.f : __expf(x);
}
__device__ __forceinline__ void split2(float v, __nv_bfloat16& hi, __nv_bfloat16& lo) {
    hi = __float2bfloat16_rn(v);
    lo = __float2bfloat16_rn(v - __bfloat162float(hi));
}

// ============================================================================
// W transpose: g_wt[n][k] = W[k][n]   (W: [512][1536])   [R5-verified]
// ============================================================================
__global__ void transpose_w(const float* __restrict__ W)
{
    __shared__ float t[32][33];
    const int bx = blockIdx.x * 32;   // n base
    const int by = blockIdx.y * 32;   // k base
    const int x = threadIdx.x;
    for (int yy = threadIdx.y; yy < 32; yy += 8)
        t[yy][x] = W[(size_t)(by + yy) * NQKV + bx + x];
    __syncthreads();
    for (int yy = threadIdx.y; yy < 32; yy += 8)
        g_wt[(size_t)(bx + yy) * 512 + by + x] = t[x][yy];
}

// ============================================================================
// Same-index elementwise split  [R6-verified]
// ============================================================================
__global__ void conv_split(const float* __restrict__ src,
                           __nv_bfloat16* __restrict__ H,
                           __nv_bfloat16* __restrict__ L)
{
    size_t i4 = (size_t)blockIdx.x * 256 + threadIdx.x;
    float4 v = ((const float4*)src)[i4];
    __nv_bfloat16 h0, h1, h2, h3, l0, l1, l2, l3;
    split2(v.x, h0, l0); split2(v.y, h1, l1); split2(v.z, h2, l2); split2(v.w, h3, l3);
    ((__nv_bfloat162*)H)[i4 * 2]     = __nv_bfloat162(h0, h1);
    ((__nv_bfloat162*)H)[i4 * 2 + 1] = __nv_bfloat162(h2, h3);
    ((__nv_bfloat162*)L)[i4 * 2]     = __nv_bfloat162(l0, l1);
    ((__nv_bfloat162*)L)[i4 * 2 + 1] = __nv_bfloat162(l2, l3);
}

// ============================================================================
// z_split: fused compute_z + conv_qz  [R8-verified]
// ============================================================================
__global__ __launch_bounds__(128) void z_split()
{
    const int row = blockIdx.x;            // 0..32767
    const int b = row >> 13;
    const int t = threadIdx.x;             // 0..127
    const int h = t >> 4;
    const int e = t * 4;
    const int d = e & 63;

    float4 q = *(const float4*)(g_q + (size_t)row * 512 + e);
    const float* ks = g_kv + (size_t)(b * 8 + h) * 4160 + 4096 + d;
    float part = q.x * ks[0] + q.y * ks[1] + q.z * ks[2] + q.w * ks[3];
#pragma unroll
    for (int off = 8; off; off >>= 1)
        part += __shfl_xor_sync(0xFFFFFFFFu, part, off);
    const float z = 1.0f / (part + 1e-6f);

    __nv_bfloat16 h0, h1, h2, h3, l0, l1, l2, l3;
    split2(q.x * z, h0, l0); split2(q.y * z, h1, l1);
    split2(q.z * z, h2, l2); split2(q.w * z, h3, l3);
    size_t o2 = ((size_t)row * 512 + e) >> 1;
    ((__nv_bfloat162*)g_qzh)[o2]     = __nv_bfloat162(h0, h1);
    ((__nv_bfloat162*)g_qzh)[o2 + 1] = __nv_bfloat162(h2, h3);
    ((__nv_bfloat162*)g_qzl)[o2]     = __nv_bfloat162(l0, l1);
    ((__nv_bfloat162*)g_qzl)[o2 + 1] = __nv_bfloat162(l2, l3);
}

// ============================================================================
// Persistent bf16-split GEMM: mma.sync + ldmatrix + cp.async double buffering.
// Grid = 296 CTAs (2/SM, single wave). Each CTA stripes tiles; at the last
// k-chunk of a tile it prefetches the NEXT tile's chunk 0, overlapping the
// epilogue + prologue with async loads. Chunk loop / fragments / epilogue are
// byte-identical to the R9-verified code. Static smem = 48KB exactly.
// MODE 0: C = X @ W -> split q/k/v, elu+1 on q,k   (tiles 12 x 256)
// MODE 1: C = (q*z) @ Wbig + bias -> Out           (tiles 4 x 256)
// ============================================================================
#define PITCH 24                      // bf16/row (48 B) -> ldmatrix conflict-free
#define ASZ   (128 * PITCH)           // elems per array (6144 B)
#define GEMM_GRID 296

template <int MODE>
__global__ __launch_bounds__(256, 2) void gemm_mma(
    const __nv_bfloat16* __restrict__ AH, const __nv_bfloat16* __restrict__ AL,
    const __nv_bfloat16* __restrict__ BHg, const __nv_bfloat16* __restrict__ BLg,
    const float* __restrict__ bias, float* __restrict__ Out)
{
    __shared__ __nv_bfloat16 smem[8 * ASZ];   // [buf][Ah,Al,Bh,Bl]

    constexpr int TN = (MODE == 0) ? 12 : 4;        // N tiles per row
    constexpr int NT = TN * 256;                    // total tiles

    const int tid = threadIdx.x;
    const int wid = tid >> 5, lane = tid & 31;
    const int g = lane >> 2, tig = lane & 3;
    const int wm = (wid & 1) * 64;
    const int wn = (wid >> 1) * 32;

    const int frow = tid >> 1, fk = (tid & 1) * 8;
    const uint32_t sOff = (uint32_t)((frow * PITCH + fk) * 2);
    const uint32_t sBase = smem_u32(smem);

    // ldmatrix per-lane offsets (bytes) [R8-verified]
    const uint32_t aoff =
        (uint32_t)(((wm + (lane & 15)) * PITCH + (lane >> 4) * 8) * 2);
    const uint32_t boff =
        (uint32_t)(((wn + ((lane >> 4) & 1) * 8 + (lane & 7)) * PITCH +
                    ((lane >> 3) & 1) * 8) * 2);

    // issue one chunk's cp.asyncs for tile (tm0, tn0) at k-offset k0 into bufI
    auto issue = [&](int tile, int k0, int bufI) {
        const int tm0 = (tile / TN) * 128;
        const int tn0 = (tile % TN) * 128;
        const __nv_bfloat16* BH = BHg + (MODE == 1 ? (size_t)(tm0 >> 13) * 262144 : 0);
        const __nv_bfloat16* BL = BLg + (MODE == 1 ? (size_t)(tm0 >> 13) * 262144 : 0);
        const uint32_t nb = sBase + (uint32_t)(bufI * 4 * ASZ * 2);
        cp16(nb + 0 * ASZ * 2 + sOff, AH + (size_t)(tm0 + frow) * 512 + fk + k0);
        cp16(nb + 1 * ASZ * 2 + sOff, AL + (size_t)(tm0 + frow) * 512 + fk + k0);
        cp16(nb + 2 * ASZ * 2 + sOff, BH + (size_t)(tn0 + frow) * 512 + fk + k0);
        cp16(nb + 3 * ASZ * 2 + sOff, BL + (size_t)(tn0 + frow) * 512 + fk + k0);
        asm volatile("cp.async.commit_group;" ::: "memory");
    };

    int buf = 0;
    bool first = true;

    for (int tile = blockIdx.x; tile < NT; tile += GEMM_GRID) {
        const int m0 = (tile / TN) * 128;
        const int n0 = (tile % TN) * 128;

        float acc[4][4][4];
#pragma unroll
        for (int i = 0; i < 4; i++)
#pragma unroll
            for (int j = 0; j < 4; j++)
#pragma unroll
                for (int t = 0; t < 4; t++) acc[i][j][t] = 0.f;

        if (first) { issue(tile, 0, buf); first = false; }

        for (int kc = 0; kc < 32; kc++) {
            asm volatile("cp.async.wait_group 0;" ::: "memory");  // chunk kc landed
            __syncthreads();   // data visible; all warps done with buf^1 reads

            // ---- issue next chunk (or next tile's chunk 0) into buf^1 ----
            if (kc < 31) {
                issue(tile, (kc + 1) * 16, buf ^ 1);
            } else if (tile + GEMM_GRID < NT) {
                issue(tile + GEMM_GRID, 0, buf ^ 1);
            }

            // ---- compute on buf: one k16, ldmatrix fragments [R8-verified] ----
            const uint32_t cb = sBase + (uint32_t)(buf * 4 * ASZ * 2);
            const uint32_t aBaseH = cb + aoff;
            const uint32_t aBaseL = cb + ASZ * 2 + aoff;
            const uint32_t bBaseH = cb + 2 * ASZ * 2 + boff;
            const uint32_t bBaseL = cb + 3 * ASZ * 2 + boff;

            uint32_t ah[4][4], al[4][4];
#pragma unroll
            for (int mt = 0; mt < 4; mt++) {
                const uint32_t ro = (uint32_t)(mt * 16 * PITCH * 2);
                ldsm4(ah[mt], aBaseH + ro);
                ldsm4(al[mt], aBaseL + ro);
            }
#pragma unroll
            for (int ntp = 0; ntp < 2; ntp++) {
                const uint32_t ro = (uint32_t)(ntp * 16 * PITCH * 2);
                uint32_t bh4[4], bl4[4];
                ldsm4(bh4, bBaseH + ro);
                ldsm4(bl4, bBaseL + ro);
#pragma unroll
                for (int half = 0; half < 2; half++) {
                    const int nt = ntp * 2 + half;
                    const uint32_t* bh = bh4 + half * 2;
                    const uint32_t* bl = bl4 + half * 2;
#pragma unroll
                    for (int mt = 0; mt < 4; mt++) {
                        mma16816(acc[mt][nt], ah[mt], bh);
                        mma16816(acc[mt][nt], ah[mt], bl);
                        mma16816(acc[mt][nt], al[mt], bh);
                    }
                }
            }
            buf ^= 1;
        }

        // -------- epilogue [R5-verified]; overlaps next tile's chunk-0 load ---
        if (MODE == 0) {
            float* dst = (n0 < 512) ? g_q : (n0 < 1024 ? g_k : g_v);
            const bool act = (n0 < 1024);
            const int cb2 = (n0 & 511) + wn;
#pragma unroll
            for (int mt = 0; mt < 4; mt++) {
                int r0 = m0 + wm + mt * 16 + g;
#pragma unroll
                for (int nt = 0; nt < 4; nt++) {
                    int c = cb2 + nt * 8 + tig * 2;
                    float v0 = acc[mt][nt][0], v1 = acc[mt][nt][1];
                    float v2 = acc[mt][nt][2], v3 = acc[mt][nt][3];
                    if (act) { v0 = elu1(v0); v1 = elu1(v1); v2 = elu1(v2); v3 = elu1(v3); }
                    *(float2*)&dst[(size_t)r0 * 512 + c]       = make_float2(v0, v1);
                    *(float2*)&dst[(size_t)(r0 + 8) * 512 + c] = make_float2(v2, v3);
                }
            }
        } else {
            const int cb2 = n0 + wn;
#pragma unroll
            for (int mt = 0; mt < 4; mt++) {
                int r0 = m0 + wm + mt * 16 + g;
#pragma unroll
                for (int nt = 0; nt < 4; nt++) {
                    int c = cb2 + nt * 8 + tig * 2;
                    float b0 = bias[c], b1 = bias[c + 1];
                    *(float2*)&Out[(size_t)r0 * 512 + c] =
                        make_float2(acc[mt][nt][0] + b0, acc[mt][nt][1] + b1);
                    *(float2*)&Out[(size_t)(r0 + 8) * 512 + c] =
                        make_float2(acc[mt][nt][2] + b0, acc[mt][nt][3] + b1);
                }
            }
        }
    }
}

// ============================================================================
// kv partial reduce + combine (fp32 SIMT) [R1/R5-verified]
// ============================================================================
__global__ __launch_bounds__(256, 4) void kv_reduce()
{
    __shared__ float ks[8][64];
    __shared__ float vs[8][64];
    const int bh = blockIdx.x;
    const int b = bh >> 3, h = bh & 7;
    const int nbase = blockIdx.y * 512;
    const int tid = threadIdx.x;
    const int tx = tid & 15, ty = tid >> 4;

    float acc[4][4];
#pragma unroll
    for (int i = 0; i < 4; i++)
#pragma unroll
        for (int j = 0; j < 4; j++) acc[i][j] = 0.f;
    float ksacc[4] = {0.f, 0.f, 0.f, 0.f};

    const int lr = (tid & 127) >> 4;
    const int lc = tid & 15;
    const float* src = (tid < 128) ? g_k : g_v;
    float* sdst = (tid < 128) ? &ks[lr][lc * 4] : &vs[lr][lc * 4];

    for (int r0 = 0; r0 < 512; r0 += 8) {
        int n = nbase + r0 + lr;
        float4 val = *(const float4*)&src[((size_t)(b * 8192 + n)) * 512 + h * 64 + lc * 4];
        *(float4*)sdst = val;
        __syncthreads();
#pragma unroll
        for (int r = 0; r < 8; r++) {
            float kf[4], vf[4];
            *(float4*)kf = *(float4*)&ks[r][tx * 4];
            *(float4*)vf = *(float4*)&vs[r][ty * 4];
#pragma unroll
            for (int i = 0; i < 4; i++)
#pragma unroll
                for (int j = 0; j < 4; j++) acc[i][j] += kf[i] * vf[j];
            if (ty == 0) {
#pragma unroll
                for (int i = 0; i < 4; i++) ksacc[i] += kf[i];
            }
        }
        __syncthreads();
    }

    const size_t base = (size_t)(bh * 16 + blockIdx.y) * 4160;
#pragma unroll
    for (int i = 0; i < 4; i++)
#pragma unroll
        for (int j = 0; j < 4; j++)
            g_kvpart[base + (tx * 4 + i) * 64 + ty * 4 + j] = acc[i][j];
    if (ty == 0) {
#pragma unroll
        for (int i = 0; i < 4; i++) g_kvpart[base + 4096 + tx * 4 + i] = ksacc[i];
    }
}

__global__ void kv_combine()
{
    const int bh = blockIdx.x;
    const int i0 = blockIdx.y * 260;
    const int iend = (i0 + 260 < 4160) ? i0 + 260 : 4160;
    for (int i = i0 + threadIdx.x; i < iend; i += 256) {
        float s = 0.f;
#pragma unroll
        for (int c = 0; c < 16; c++) s += g_kvpart[(size_t)(bh * 16 + c) * 4160 + i];
        g_kv[(size_t)bh * 4160 + i] = s;
    }
}

// ============================================================================
// Wbig^T bf16 hi/lo  [R6-verified]
// ============================================================================
__global__ void make_wbig(const float* __restrict__ Wout)
{
    const int r = blockIdx.x;          // h*64+d
    const int b = blockIdx.y;
    const int h = r >> 6, d = r & 63;
    __shared__ float kvrow[64];
    if (threadIdx.x < 64)
        kvrow[threadIdx.x] = g_kv[(size_t)(b * 8 + h) * 4160 + d * 64 + threadIdx.x];
    __syncthreads();
    float acc[4] = {0.f, 0.f, 0.f, 0.f};
    for (int m = 0; m < 64; m++) {
        float kvv = kvrow[m];
        const float* wrow = Wout + (size_t)(h * 64 + m) * 512;
#pragma unroll
        for (int i = 0; i < 4; i++) acc[i] += kvv * wrow[threadIdx.x + i * 128];
    }
#pragma unroll
    for (int i = 0; i < 4; i++) {
        int j = threadIdx.x + i * 128;
        __nv_bfloat16 hi, lo;
        split2(acc[i], hi, lo);
        g_wbth[(size_t)b * 262144 + (size_t)j * 512 + r] = hi;
        g_wbtl[(size_t)b * 262144 + (size_t)j * 512 + r] = lo;
    }
}

// ============================================================================
extern "C" void kernel_launch(void* const* d_in, const int* in_sizes, int n_in,
                              void* d_out, int out_size)
{
    const float* x     = (const float*)d_in[0];   // [4,8192,512]
    const float* w_qkv = (const float*)d_in[1];   // [512,1536]
    const float* w_out = (const float*)d_in[2];   // [512,512]
    const float* b_out = (const float*)d_in[3];   // [512]
    float* out = (float*)d_out;                   // [4,8192,512]

    float* wt_p;    cudaGetSymbolAddress((void**)&wt_p,  g_wt);
    __nv_bfloat16 *xh_p, *xl_p, *wth_p, *wtl_p, *qzh_p, *qzl_p, *wbth_p, *wbtl_p;
    cudaGetSymbolAddress((void**)&xh_p,  g_xh);
    cudaGetSymbolAddress((void**)&xl_p,  g_xl);
    cudaGetSymbolAddress((void**)&wth_p, g_wth);
    cudaGetSymbolAddress((void**)&wtl_p, g_wtl);
    cudaGetSymbolAddress((void**)&qzh_p, g_qzh);
    cudaGetSymbolAddress((void**)&qzl_p, g_qzl);
    cudaGetSymbolAddress((void**)&wbth_p, g_wbth);
    cudaGetSymbolAddress((void**)&wbtl_p, g_wbtl);

    transpose_w<<<dim3(48, 16), dim3(32, 8)>>>(w_qkv);
    conv_split<<<16384, 256>>>(x, xh_p, xl_p);                 // X
    conv_split<<<768, 256>>>(wt_p, wth_p, wtl_p);              // W^T
    gemm_mma<0><<<GEMM_GRID, 256>>>(xh_p, xl_p, wth_p, wtl_p, nullptr, nullptr);
    kv_reduce<<<dim3(32, 16), 256>>>();
    kv_combine<<<dim3(32, 16), 256>>>();
    make_wbig<<<dim3(512, 4), 128>>>(w_out);
    z_split<<<32768, 128>>>();
    gemm_mma<1><<<GEMM_GRID, 256>>>(qzh_p, qzl_p, wbth_p, wbtl_p, b_out, out);
}

// round 11
// speedup vs baseline: 1.0903x; 1.0903x over previous
#include <cuda_runtime.h>
#include <cuda_bf16.h>
#include <math.h>
#include <stdint.h>

#define MROWS (4 * 8192)          // 32768 rows total
#define DIMK  512
#define NQKV  1536

// ---------------- scratch (device globals; no allocation allowed) ----------
__device__ float g_q[MROWS * 512];          // elu(q)+1 fp32
__device__ float g_k[MROWS * 512];          // elu(k)+1 fp32
__device__ float g_v[MROWS * 512];          // v fp32
__device__ float g_kvpart[32 * 16 * 4160];  // per (bh,chunk): 64x64 kv + 64 ksum
__device__ float g_kv[32 * 4160];
__device__ float g_wt[NQKV * 512];          // w_qkv^T fp32 [n][k]

__device__ __nv_bfloat16 g_xh[MROWS * 512];   // x hi/lo (same index as x)
__device__ __nv_bfloat16 g_xl[MROWS * 512];
__device__ __nv_bfloat16 g_wth[NQKV * 512];   // w^T hi/lo (same index as g_wt)
__device__ __nv_bfloat16 g_wtl[NQKV * 512];
__device__ __nv_bfloat16 g_qzh[MROWS * 512];  // (q*z) hi/lo (same index as g_q)
__device__ __nv_bfloat16 g_qzl[MROWS * 512];
__device__ __nv_bfloat16 g_wbth[4 * 512 * 512]; // Wbig^T hi/lo [b][j][r]
__device__ __nv_bfloat16 g_wbtl[4 * 512 * 512];

// ---------------- helpers ---------------------------------------------------
__device__ __forceinline__ void mma16816(float* c, const uint32_t* a, const uint32_t* b) {
    asm volatile(
        "mma.sync.aligned.m16n8k16.row.col.f32.bf16.bf16.f32 "
        "{%0,%1,%2,%3}, {%4,%5,%6,%7}, {%8,%9}, {%0,%1,%2,%3};"
        : "+f"(c[0]), "+f"(c[1]), "+f"(c[2]), "+f"(c[3])
        : "r"(a[0]), "r"(a[1]), "r"(a[2]), "r"(a[3]), "r"(b[0]), "r"(b[1]));
}
__device__ __forceinline__ void ldsm4(uint32_t* r, uint32_t a) {
    asm volatile("ldmatrix.sync.aligned.m8n8.x4.shared.b16 {%0,%1,%2,%3}, [%4];"
        : "=r"(r[0]), "=r"(r[1]), "=r"(r[2]), "=r"(r[3]) : "r"(a));
}
__device__ __forceinline__ uint32_t smem_u32(const void* p) {
    uint32_t a;
    asm("{ .reg .u64 t; cvta.to.shared.u64 t, %1; cvt.u32.u64 %0, t; }" : "=r"(a) : "l"(p));
    return a;
}
__device__ __forceinline__ void cp16(uint32_t s, const void* g) {
    asm volatile("cp.async.cg.shared.global [%0], [%1], 16;" :: "r"(s), "l"(g));
}
__device__ __forceinline__ float elu1(float x) {
    return x >= 0.f ? x + 1.f : __expf(x);
}
__device__ __forceinline__ void split2(float v, __nv_bfloat16& hi, __nv_bfloat16& lo) {
    hi = __float2bfloat16_rn(v);
    lo = __float2bfloat16_rn(v - __bfloat162float(hi));
}

// ============================================================================
// W transpose: g_wt[n][k] = W[k][n]   (W: [512][1536])   [R5-verified]
// ============================================================================
__global__ void transpose_w(const float* __restrict__ W)
{
    __shared__ float t[32][33];
    const int bx = blockIdx.x * 32;   // n base
    const int by = blockIdx.y * 32;   // k base
    const int x = threadIdx.x;
    for (int yy = threadIdx.y; yy < 32; yy += 8)
        t[yy][x] = W[(size_t)(by + yy) * NQKV + bx + x];
    __syncthreads();
    for (int yy = threadIdx.y; yy < 32; yy += 8)
        g_wt[(size_t)(bx + yy) * 512 + by + x] = t[x][yy];
}

// ============================================================================
// Same-index elementwise split  [R6-verified]
// ============================================================================
__global__ void conv_split(const float* __restrict__ src,
                           __nv_bfloat16* __restrict__ H,
                           __nv_bfloat16* __restrict__ L)
{
    size_t i4 = (size_t)blockIdx.x * 256 + threadIdx.x;
    float4 v = ((const float4*)src)[i4];
    __nv_bfloat16 h0, h1, h2, h3, l0, l1, l2, l3;
    split2(v.x, h0, l0); split2(v.y, h1, l1); split2(v.z, h2, l2); split2(v.w, h3, l3);
    ((__nv_bfloat162*)H)[i4 * 2]     = __nv_bfloat162(h0, h1);
    ((__nv_bfloat162*)H)[i4 * 2 + 1] = __nv_bfloat162(h2, h3);
    ((__nv_bfloat162*)L)[i4 * 2]     = __nv_bfloat162(l0, l1);
    ((__nv_bfloat162*)L)[i4 * 2 + 1] = __nv_bfloat162(l2, l3);
}

// ============================================================================
// z_split: fused compute_z + conv_qz  [R8-verified]
// ============================================================================
__global__ __launch_bounds__(128) void z_split()
{
    const int row = blockIdx.x;            // 0..32767
    const int b = row >> 13;
    const int t = threadIdx.x;             // 0..127
    const int h = t >> 4;
    const int e = t * 4;
    const int d = e & 63;

    float4 q = *(const float4*)(g_q + (size_t)row * 512 + e);
    const float* ks = g_kv + (size_t)(b * 8 + h) * 4160 + 4096 + d;
    float part = q.x * ks[0] + q.y * ks[1] + q.z * ks[2] + q.w * ks[3];
#pragma unroll
    for (int off = 8; off; off >>= 1)
        part += __shfl_xor_sync(0xFFFFFFFFu, part, off);
    const float z = 1.0f / (part + 1e-6f);

    __nv_bfloat16 h0, h1, h2, h3, l0, l1, l2, l3;
    split2(q.x * z, h0, l0); split2(q.y * z, h1, l1);
    split2(q.z * z, h2, l2); split2(q.w * z, h3, l3);
    size_t o2 = ((size_t)row * 512 + e) >> 1;
    ((__nv_bfloat162*)g_qzh)[o2]     = __nv_bfloat162(h0, h1);
    ((__nv_bfloat162*)g_qzh)[o2 + 1] = __nv_bfloat162(h2, h3);
    ((__nv_bfloat162*)g_qzl)[o2]     = __nv_bfloat162(l0, l1);
    ((__nv_bfloat162*)g_qzl)[o2 + 1] = __nv_bfloat162(l2, l3);
}

// ============================================================================
// bf16-split GEMM: mma.sync + ldmatrix + 3-stage cp.async pipeline.
// C tile 128x128, K=512 in 32 chunks of 16. XOR-swizzled 32B rows (no pad):
// slot(row, k8) = k8 ^ ((row>>2)&1); chunk buffer = 4 arrays x 4096B = 16KB;
// 3 buffers = 48KB static smem exactly. Depth-2 latency hiding (wait_group 1).
// Fragment logical mapping and epilogue identical to R9-verified code.
// MODE 0: C = X @ W -> split q/k/v, elu+1 on q,k   (grid 12 x 256)
// MODE 1: C = (q*z) @ Wbig + bias -> Out           (grid 4 x 256)
// ============================================================================
#define ABYTES 4096                    // one array: 128 rows x 32 B
#define BUFB   (4 * ABYTES)            // Ah,Al,Bh,Bl per chunk = 16384 B

template <int MODE>
__global__ __launch_bounds__(256, 2) void gemm_mma(
    const __nv_bfloat16* __restrict__ AH, const __nv_bfloat16* __restrict__ AL,
    const __nv_bfloat16* __restrict__ BHg, const __nv_bfloat16* __restrict__ BLg,
    const float* __restrict__ bias, float* __restrict__ Out)
{
    __shared__ __nv_bfloat16 smem[3 * BUFB / 2];   // 48 KB

    const int tid = threadIdx.x;
    const int wid = tid >> 5, lane = tid & 31;
    const int g = lane >> 2, tig = lane & 3;
    const int m0 = blockIdx.y * 128;
    const int n0 = blockIdx.x * 128;
    const int wm = (wid & 1) * 64;
    const int wn = (wid >> 1) * 32;
    const int bb = m0 >> 13;          // batch (tiles never straddle batches)

    const __nv_bfloat16* BH = BHg + (MODE == 1 ? (size_t)bb * 262144 : 0);
    const __nv_bfloat16* BL = BLg + (MODE == 1 ? (size_t)bb * 262144 : 0);

    // fill mapping: thread t -> row = t>>1, k8-group j = t&1, swizzled slot
    const int frow = tid >> 1, fj = tid & 1;
    const int fslot = fj ^ ((frow >> 2) & 1);
    const uint32_t sOff = (uint32_t)(frow * 32 + fslot * 16);
    const __nv_bfloat16* gah = AH + (size_t)(m0 + frow) * 512 + fj * 8;
    const __nv_bfloat16* gal = AL + (size_t)(m0 + frow) * 512 + fj * 8;
    const __nv_bfloat16* gbh = BH + (size_t)(n0 + frow) * 512 + fj * 8;
    const __nv_bfloat16* gbl = BL + (size_t)(n0 + frow) * 512 + fj * 8;

    const uint32_t sBase = smem_u32(smem);

    // ldmatrix per-lane offsets (swizzled slot; invariant across mt/ntp since
    // those shift rows by multiples of 16 and wm/wn by multiples of 32)
    const int ar = lane & 15, akh = lane >> 4;
    const uint32_t aoff =
        (uint32_t)((wm + ar) * 32 + ((akh ^ ((ar >> 2) & 1)) * 16));
    const int brl = ((lane >> 4) & 1) * 8 + (lane & 7);
    const int bkh = (lane >> 3) & 1;
    const uint32_t boff =
        (uint32_t)((wn + brl) * 32 + ((bkh ^ (((lane & 7) >> 2) & 1)) * 16));

    // issue one chunk's cp.asyncs (k-offset k0) into buffer bufI
    auto issue = [&](int k0, int bufI) {
        const uint32_t nb = sBase + (uint32_t)(bufI * BUFB);
        cp16(nb + 0 * ABYTES + sOff, gah + k0);
        cp16(nb + 1 * ABYTES + sOff, gal + k0);
        cp16(nb + 2 * ABYTES + sOff, gbh + k0);
        cp16(nb + 3 * ABYTES + sOff, gbl + k0);
        asm volatile("cp.async.commit_group;" ::: "memory");
    };

    float acc[4][4][4];
#pragma unroll
    for (int i = 0; i < 4; i++)
#pragma unroll
        for (int j = 0; j < 4; j++)
#pragma unroll
            for (int t = 0; t < 4; t++) acc[i][j][t] = 0.f;

    // ---- prologue: chunks 0,1 into buffers 0,1 ----
    issue(0, 0);
    issue(16, 1);

    for (int kc = 0; kc < 32; kc++) {
        if (kc < 31) {
            asm volatile("cp.async.wait_group 1;" ::: "memory");  // chunk kc landed
        } else {
            asm volatile("cp.async.wait_group 0;" ::: "memory");
        }
        __syncthreads();   // data visible; all warps done reading buf[(kc+2)%3]

        // ---- issue chunk kc+2 into buffer (kc+2)%3 (overlaps compute) ----
        if (kc < 30) issue((kc + 2) * 16, (kc + 2) % 3);

        // ---- compute on buffer kc%3: one k16, ldmatrix fragments ----
        const uint32_t cb = sBase + (uint32_t)((kc % 3) * BUFB);
        const uint32_t aBaseH = cb + aoff;
        const uint32_t aBaseL = cb + ABYTES + aoff;
        const uint32_t bBaseH = cb + 2 * ABYTES + boff;
        const uint32_t bBaseL = cb + 3 * ABYTES + boff;

        uint32_t ah[4][4], al[4][4];
#pragma unroll
        for (int mt = 0; mt < 4; mt++) {
            const uint32_t ro = (uint32_t)(mt * 512);   // 16 rows * 32 B
            ldsm4(ah[mt], aBaseH + ro);
            ldsm4(al[mt], aBaseL + ro);
        }
#pragma unroll
        for (int ntp = 0; ntp < 2; ntp++) {
            const uint32_t ro = (uint32_t)(ntp * 512);
            uint32_t bh4[4], bl4[4];
            ldsm4(bh4, bBaseH + ro);
            ldsm4(bl4, bBaseL + ro);
#pragma unroll
            for (int half = 0; half < 2; half++) {
                const int nt = ntp * 2 + half;
                const uint32_t* bh = bh4 + half * 2;
                const uint32_t* bl = bl4 + half * 2;
#pragma unroll
                for (int mt = 0; mt < 4; mt++) {
                    mma16816(acc[mt][nt], ah[mt], bh);
                    mma16816(acc[mt][nt], ah[mt], bl);
                    mma16816(acc[mt][nt], al[mt], bh);
                }
            }
        }
    }

    // -------- epilogue [R5-verified] --------
    if (MODE == 0) {
        float* dst = (n0 < 512) ? g_q : (n0 < 1024 ? g_k : g_v);
        const bool act = (n0 < 1024);
        const int cb2 = (n0 & 511) + wn;
#pragma unroll
        for (int mt = 0; mt < 4; mt++) {
            int r0 = m0 + wm + mt * 16 + g;
#pragma unroll
            for (int nt = 0; nt < 4; nt++) {
                int c = cb2 + nt * 8 + tig * 2;
                float v0 = acc[mt][nt][0], v1 = acc[mt][nt][1];
                float v2 = acc[mt][nt][2], v3 = acc[mt][nt][3];
                if (act) { v0 = elu1(v0); v1 = elu1(v1); v2 = elu1(v2); v3 = elu1(v3); }
                *(float2*)&dst[(size_t)r0 * 512 + c]       = make_float2(v0, v1);
                *(float2*)&dst[(size_t)(r0 + 8) * 512 + c] = make_float2(v2, v3);
            }
        }
    } else {
        const int cb2 = n0 + wn;
#pragma unroll
        for (int mt = 0; mt < 4; mt++) {
            int r0 = m0 + wm + mt * 16 + g;
#pragma unroll
            for (int nt = 0; nt < 4; nt++) {
                int c = cb2 + nt * 8 + tig * 2;
                float b0 = bias[c], b1 = bias[c + 1];
                *(float2*)&Out[(size_t)r0 * 512 + c] =
                    make_float2(acc[mt][nt][0] + b0, acc[mt][nt][1] + b1);
                *(float2*)&Out[(size_t)(r0 + 8) * 512 + c] =
                    make_float2(acc[mt][nt][2] + b0, acc[mt][nt][3] + b1);
            }
        }
    }
}

// ============================================================================
// kv partial reduce + combine (fp32 SIMT) [R1/R5-verified]
// ============================================================================
__global__ __launch_bounds__(256, 4) void kv_reduce()
{
    __shared__ float ks[8][64];
    __shared__ float vs[8][64];
    const int bh = blockIdx.x;
    const int b = bh >> 3, h = bh & 7;
    const int nbase = blockIdx.y * 512;
    const int tid = threadIdx.x;
    const int tx = tid & 15, ty = tid >> 4;

    float acc[4][4];
#pragma unroll
    for (int i = 0; i < 4; i++)
#pragma unroll
        for (int j = 0; j < 4; j++) acc[i][j] = 0.f;
    float ksacc[4] = {0.f, 0.f, 0.f, 0.f};

    const int lr = (tid & 127) >> 4;
    const int lc = tid & 15;
    const float* src = (tid < 128) ? g_k : g_v;
    float* sdst = (tid < 128) ? &ks[lr][lc * 4] : &vs[lr][lc * 4];

    for (int r0 = 0; r0 < 512; r0 += 8) {
        int n = nbase + r0 + lr;
        float4 val = *(const float4*)&src[((size_t)(b * 8192 + n)) * 512 + h * 64 + lc * 4];
        *(float4*)sdst = val;
        __syncthreads();
#pragma unroll
        for (int r = 0; r < 8; r++) {
            float kf[4], vf[4];
            *(float4*)kf = *(float4*)&ks[r][tx * 4];
            *(float4*)vf = *(float4*)&vs[r][ty * 4];
#pragma unroll
            for (int i = 0; i < 4; i++)
#pragma unroll
                for (int j = 0; j < 4; j++) acc[i][j] += kf[i] * vf[j];
            if (ty == 0) {
#pragma unroll
                for (int i = 0; i < 4; i++) ksacc[i] += kf[i];
            }
        }
        __syncthreads();
    }

    const size_t base = (size_t)(bh * 16 + blockIdx.y) * 4160;
#pragma unroll
    for (int i = 0; i < 4; i++)
#pragma unroll
        for (int j = 0; j < 4; j++)
            g_kvpart[base + (tx * 4 + i) * 64 + ty * 4 + j] = acc[i][j];
    if (ty == 0) {
#pragma unroll
        for (int i = 0; i < 4; i++) g_kvpart[base + 4096 + tx * 4 + i] = ksacc[i];
    }
}

__global__ void kv_combine()
{
    const int bh = blockIdx.x;
    const int i0 = blockIdx.y * 260;
    const int iend = (i0 + 260 < 4160) ? i0 + 260 : 4160;
    for (int i = i0 + threadIdx.x; i < iend; i += 256) {
        float s = 0.f;
#pragma unroll
        for (int c = 0; c < 16; c++) s += g_kvpart[(size_t)(bh * 16 + c) * 4160 + i];
        g_kv[(size_t)bh * 4160 + i] = s;
    }
}

// ============================================================================
// Wbig^T bf16 hi/lo  [R6-verified]
// ============================================================================
__global__ void make_wbig(const float* __restrict__ Wout)
{
    const int r = blockIdx.x;          // h*64+d
    const int b = blockIdx.y;
    const int h = r >> 6, d = r & 63;
    __shared__ float kvrow[64];
    if (threadIdx.x < 64)
        kvrow[threadIdx.x] = g_kv[(size_t)(b * 8 + h) * 4160 + d * 64 + threadIdx.x];
    __syncthreads();
    float acc[4] = {0.f, 0.f, 0.f, 0.f};
    for (int m = 0; m < 64; m++) {
        float kvv = kvrow[m];
        const float* wrow = Wout + (size_t)(h * 64 + m) * 512;
#pragma unroll
        for (int i = 0; i < 4; i++) acc[i] += kvv * wrow[threadIdx.x + i * 128];
    }
#pragma unroll
    for (int i = 0; i < 4; i++) {
        int j = threadIdx.x + i * 128;
        __nv_bfloat16 hi, lo;
        split2(acc[i], hi, lo);
        g_wbth[(size_t)b * 262144 + (size_t)j * 512 + r] = hi;
        g_wbtl[(size_t)b * 262144 + (size_t)j * 512 + r] = lo;
    }
}

// ============================================================================
extern "C" void kernel_launch(void* const* d_in, const int* in_sizes, int n_in,
                              void* d_out, int out_size)
{
    const float* x     = (const float*)d_in[0];   // [4,8192,512]
    const float* w_qkv = (const float*)d_in[1];   // [512,1536]
    const float* w_out = (const float*)d_in[2];   // [512,512]
    const float* b_out = (const float*)d_in[3];   // [512]
    float* out = (float*)d_out;                   // [4,8192,512]

    float* wt_p;    cudaGetSymbolAddress((void**)&wt_p,  g_wt);
    __nv_bfloat16 *xh_p, *xl_p, *wth_p, *wtl_p, *qzh_p, *qzl_p, *wbth_p, *wbtl_p;
    cudaGetSymbolAddress((void**)&xh_p,  g_xh);
    cudaGetSymbolAddress((void**)&xl_p,  g_xl);
    cudaGetSymbolAddress((void**)&wth_p, g_wth);
    cudaGetSymbolAddress((void**)&wtl_p, g_wtl);
    cudaGetSymbolAddress((void**)&qzh_p, g_qzh);
    cudaGetSymbolAddress((void**)&qzl_p, g_qzl);
    cudaGetSymbolAddress((void**)&wbth_p, g_wbth);
    cudaGetSymbolAddress((void**)&wbtl_p, g_wbtl);

    transpose_w<<<dim3(48, 16), dim3(32, 8)>>>(w_qkv);
    conv_split<<<16384, 256>>>(x, xh_p, xl_p);                 // X
    conv_split<<<768, 256>>>(wt_p, wth_p, wtl_p);              // W^T
    gemm_mma<0><<<dim3(12, 256), 256>>>(xh_p, xl_p, wth_p, wtl_p, nullptr, nullptr);
    kv_reduce<<<dim3(32, 16), 256>>>();
    kv_combine<<<dim3(32, 16), 256>>>();
    make_wbig<<<dim3(512, 4), 128>>>(w_out);
    z_split<<<32768, 128>>>();
    gemm_mma<1><<<dim3(4, 256), 256>>>(qzh_p, qzl_p, wbth_p, wbtl_p, b_out, out);
}

// round 12
// speedup vs baseline: 1.4045x; 1.2881x over previous
#include <cuda_runtime.h>
#include <cuda_bf16.h>
#include <cuda_fp16.h>
#include <math.h>
#include <stdint.h>

#define MROWS (4 * 8192)          // 32768 rows total
#define DIMK  512
#define NQKV  1536

// ---------------- scratch (device globals; no allocation allowed) ----------
__device__ float g_q[MROWS * 512];          // elu(q)+1 fp32
__device__ float g_k[MROWS * 512];          // elu(k)+1 fp32
__device__ float g_v[MROWS * 512];          // v fp32
__device__ float g_kvpart[32 * 16 * 4160];  // per (bh,chunk): 64x64 kv + 64 ksum
__device__ float g_kv[32 * 4160];
__device__ float g_wt[NQKV * 512];          // w_qkv^T fp32 [n][k]

__device__ __half g_xf[MROWS * 512];          // x single fp16
__device__ __half g_wfh[NQKV * 512];          // (16*w^T) hi fp16
__device__ __half g_wfl[NQKV * 512];          // (16*w^T) lo fp16
__device__ __nv_bfloat16 g_qzh[MROWS * 512];  // (q*z) hi/lo bf16
__device__ __nv_bfloat16 g_qzl[MROWS * 512];
__device__ __nv_bfloat16 g_wbth[4 * 512 * 512]; // Wbig^T hi/lo [b][j][r]
__device__ __nv_bfloat16 g_wbtl[4 * 512 * 512];

// ---------------- helpers ---------------------------------------------------
__device__ __forceinline__ void mma16816(float* c, const uint32_t* a, const uint32_t* b) {
    asm volatile(
        "mma.sync.aligned.m16n8k16.row.col.f32.bf16.bf16.f32 "
        "{%0,%1,%2,%3}, {%4,%5,%6,%7}, {%8,%9}, {%0,%1,%2,%3};"
        : "+f"(c[0]), "+f"(c[1]), "+f"(c[2]), "+f"(c[3])
        : "r"(a[0]), "r"(a[1]), "r"(a[2]), "r"(a[3]), "r"(b[0]), "r"(b[1]));
}
__device__ __forceinline__ void mma16816h(float* c, const uint32_t* a, const uint32_t* b) {
    asm volatile(
        "mma.sync.aligned.m16n8k16.row.col.f32.f16.f16.f32 "
        "{%0,%1,%2,%3}, {%4,%5,%6,%7}, {%8,%9}, {%0,%1,%2,%3};"
        : "+f"(c[0]), "+f"(c[1]), "+f"(c[2]), "+f"(c[3])
        : "r"(a[0]), "r"(a[1]), "r"(a[2]), "r"(a[3]), "r"(b[0]), "r"(b[1]));
}
__device__ __forceinline__ void ldsm4(uint32_t* r, uint32_t a) {
    asm volatile("ldmatrix.sync.aligned.m8n8.x4.shared.b16 {%0,%1,%2,%3}, [%4];"
        : "=r"(r[0]), "=r"(r[1]), "=r"(r[2]), "=r"(r[3]) : "r"(a));
}
__device__ __forceinline__ uint32_t smem_u32(const void* p) {
    uint32_t a;
    asm("{ .reg .u64 t; cvta.to.shared.u64 t, %1; cvt.u32.u64 %0, t; }" : "=r"(a) : "l"(p));
    return a;
}
__device__ __forceinline__ void cp16(uint32_t s, const void* g) {
    asm volatile("cp.async.cg.shared.global [%0], [%1], 16;" :: "r"(s), "l"(g));
}
__device__ __forceinline__ float elu1(float x) {
    return x >= 0.f ? x + 1.f : __expf(x);
}
__device__ __forceinline__ void split2(float v, __nv_bfloat16& hi, __nv_bfloat16& lo) {
    hi = __float2bfloat16_rn(v);
    lo = __float2bfloat16_rn(v - __bfloat162float(hi));
}

// ============================================================================
// W transpose: g_wt[n][k] = W[k][n]   (W: [512][1536])   [R5-verified]
// ============================================================================
__global__ void transpose_w(const float* __restrict__ W)
{
    __shared__ float t[32][33];
    const int bx = blockIdx.x * 32;   // n base
    const int by = blockIdx.y * 32;   // k base
    const int x = threadIdx.x;
    for (int yy = threadIdx.y; yy < 32; yy += 8)
        t[yy][x] = W[(size_t)(by + yy) * NQKV + bx + x];
    __syncthreads();
    for (int yy = threadIdx.y; yy < 32; yy += 8)
        g_wt[(size_t)(bx + yy) * 512 + by + x] = t[x][yy];
}

// ============================================================================
// conv_x_f16: X fp32 -> single fp16 (same index)
// ============================================================================
__global__ void conv_x_f16(const float* __restrict__ X)
{
    size_t i4 = (size_t)blockIdx.x * 256 + threadIdx.x;
    float4 v = ((const float4*)X)[i4];
    __half2* O = (__half2*)g_xf;
    O[i4 * 2]     = __floats2half2_rn(v.x, v.y);
    O[i4 * 2 + 1] = __floats2half2_rn(v.z, v.w);
}

// ============================================================================
// conv_w_f16: g_wt fp32 -> fp16 hi/lo of (16*w)  (same index)
// ============================================================================
__global__ void conv_w_f16()
{
    size_t i = (size_t)blockIdx.x * 256 + threadIdx.x;
    float v = g_wt[i] * 16.0f;
    __half hi = __float2half_rn(v);
    __half lo = __float2half_rn(v - __half2float(hi));
    g_wfh[i] = hi;
    g_wfl[i] = lo;
}

// ============================================================================
// z_split: fused compute_z + conv_qz  [R8-verified]
// ============================================================================
__global__ __launch_bounds__(128) void z_split()
{
    const int row = blockIdx.x;            // 0..32767
    const int b = row >> 13;
    const int t = threadIdx.x;             // 0..127
    const int h = t >> 4;
    const int e = t * 4;
    const int d = e & 63;

    float4 q = *(const float4*)(g_q + (size_t)row * 512 + e);
    const float* ks = g_kv + (size_t)(b * 8 + h) * 4160 + 4096 + d;
    float part = q.x * ks[0] + q.y * ks[1] + q.z * ks[2] + q.w * ks[3];
#pragma unroll
    for (int off = 8; off; off >>= 1)
        part += __shfl_xor_sync(0xFFFFFFFFu, part, off);
    const float z = 1.0f / (part + 1e-6f);

    __nv_bfloat16 h0, h1, h2, h3, l0, l1, l2, l3;
    split2(q.x * z, h0, l0); split2(q.y * z, h1, l1);
    split2(q.z * z, h2, l2); split2(q.w * z, h3, l3);
    size_t o2 = ((size_t)row * 512 + e) >> 1;
    ((__nv_bfloat162*)g_qzh)[o2]     = __nv_bfloat162(h0, h1);
    ((__nv_bfloat162*)g_qzh)[o2 + 1] = __nv_bfloat162(h2, h3);
    ((__nv_bfloat162*)g_qzl)[o2]     = __nv_bfloat162(l0, l1);
    ((__nv_bfloat162*)g_qzl)[o2 + 1] = __nv_bfloat162(l2, l3);
}

// ============================================================================
// GEMM 0 (fp16 2-product): C = X @ (Wh+Wl)/16 -> q/k/v with elu+1 on q,k.
// A single fp16, B split fp16 (x16 pre-scale). C tile 128x128, K=512 in 32
// chunks of 16. XOR-swizzled 32B rows; chunk buffer = 3 arrays x 4096B = 12KB;
// 4 buffers = 48KB static smem. 4-stage cp.async pipeline (depth-3 hiding).
// Fragment mapping identical to R11-verified ldsm scheme.
// ============================================================================
#define ABYTES 4096                    // one array: 128 rows x 32 B

__global__ __launch_bounds__(256, 2) void gemm_f16(
    const __half* __restrict__ Ag, const __half* __restrict__ BHg,
    const __half* __restrict__ BLg)
{
#define BUF0B (3 * ABYTES)             // 12288 B per chunk buffer
    __shared__ __half smem[4 * BUF0B / 2];   // 48 KB

    const int tid = threadIdx.x;
    const int wid = tid >> 5, lane = tid & 31;
    const int g = lane >> 2, tig = lane & 3;
    const int m0 = blockIdx.y * 128;
    const int n0 = blockIdx.x * 128;
    const int wm = (wid & 1) * 64;
    const int wn = (wid >> 1) * 32;

    // fill mapping: thread t -> row = t>>1, k8-group j = t&1, swizzled slot
    const int frow = tid >> 1, fj = tid & 1;
    const int fslot = fj ^ ((frow >> 2) & 1);
    const uint32_t sOff = (uint32_t)(frow * 32 + fslot * 16);
    const __half* ga  = Ag  + (size_t)(m0 + frow) * 512 + fj * 8;
    const __half* gbh = BHg + (size_t)(n0 + frow) * 512 + fj * 8;
    const __half* gbl = BLg + (size_t)(n0 + frow) * 512 + fj * 8;

    const uint32_t sBase = smem_u32(smem);

    // ldmatrix per-lane offsets [R11-verified swizzle]
    const int ar = lane & 15, akh = lane >> 4;
    const uint32_t aoff =
        (uint32_t)((wm + ar) * 32 + ((akh ^ ((ar >> 2) & 1)) * 16));
    const int brl = ((lane >> 4) & 1) * 8 + (lane & 7);
    const int bkh = (lane >> 3) & 1;
    const uint32_t boff =
        (uint32_t)((wn + brl) * 32 + ((bkh ^ (((lane & 7) >> 2) & 1)) * 16));

    auto issue = [&](int k0, int bufI) {
        const uint32_t nb = sBase + (uint32_t)(bufI * BUF0B);
        cp16(nb + 0 * ABYTES + sOff, ga + k0);
        cp16(nb + 1 * ABYTES + sOff, gbh + k0);
        cp16(nb + 2 * ABYTES + sOff, gbl + k0);
        asm volatile("cp.async.commit_group;" ::: "memory");
    };

    float acc[4][4][4];
#pragma unroll
    for (int i = 0; i < 4; i++)
#pragma unroll
        for (int j = 0; j < 4; j++)
#pragma unroll
            for (int t = 0; t < 4; t++) acc[i][j][t] = 0.f;

    // ---- prologue: chunks 0,1,2 into buffers 0,1,2 ----
    issue(0, 0);
    issue(16, 1);
    issue(32, 2);

    for (int kc = 0; kc < 32; kc++) {
        if (kc < 30) {
            asm volatile("cp.async.wait_group 2;" ::: "memory");
        } else if (kc == 30) {
            asm volatile("cp.async.wait_group 1;" ::: "memory");
        } else {
            asm volatile("cp.async.wait_group 0;" ::: "memory");
        }
        __syncthreads();   // chunk kc visible; all warps done with buf (kc+3)&3

        if (kc <= 28) issue((kc + 3) * 16, (kc + 3) & 3);

        const uint32_t cb = sBase + (uint32_t)((kc & 3) * BUF0B);
        const uint32_t aBase  = cb + aoff;
        const uint32_t bBaseH = cb + 1 * ABYTES + boff;
        const uint32_t bBaseL = cb + 2 * ABYTES + boff;

        uint32_t a4[4][4];
#pragma unroll
        for (int mt = 0; mt < 4; mt++)
            ldsm4(a4[mt], aBase + (uint32_t)(mt * 512));
#pragma unroll
        for (int ntp = 0; ntp < 2; ntp++) {
            const uint32_t ro = (uint32_t)(ntp * 512);
            uint32_t bh4[4], bl4[4];
            ldsm4(bh4, bBaseH + ro);
            ldsm4(bl4, bBaseL + ro);
#pragma unroll
            for (int half = 0; half < 2; half++) {
                const int nt = ntp * 2 + half;
                const uint32_t* bh = bh4 + half * 2;
                const uint32_t* bl = bl4 + half * 2;
#pragma unroll
                for (int mt = 0; mt < 4; mt++) {
                    mma16816h(acc[mt][nt], a4[mt], bl);
                    mma16816h(acc[mt][nt], a4[mt], bh);
                }
            }
        }
    }

    // -------- epilogue: scale 1/16, split q/k/v, elu+1 on q,k --------
    {
        float* dst = (n0 < 512) ? g_q : (n0 < 1024 ? g_k : g_v);
        const bool act = (n0 < 1024);
        const int cb2 = (n0 & 511) + wn;
        const float sc = 1.0f / 16.0f;
#pragma unroll
        for (int mt = 0; mt < 4; mt++) {
            int r0 = m0 + wm + mt * 16 + g;
#pragma unroll
            for (int nt = 0; nt < 4; nt++) {
                int c = cb2 + nt * 8 + tig * 2;
                float v0 = acc[mt][nt][0] * sc, v1 = acc[mt][nt][1] * sc;
                float v2 = acc[mt][nt][2] * sc, v3 = acc[mt][nt][3] * sc;
                if (act) { v0 = elu1(v0); v1 = elu1(v1); v2 = elu1(v2); v3 = elu1(v3); }
                *(float2*)&dst[(size_t)r0 * 512 + c]       = make_float2(v0, v1);
                *(float2*)&dst[(size_t)(r0 + 8) * 512 + c] = make_float2(v2, v3);
            }
        }
    }
}

// ============================================================================
// GEMM 1 (bf16 3-product) [R11-verified]: C = (q*z) @ Wbig + bias -> Out
// 3-stage pipeline, 3 buffers x 16KB = 48KB.
// ============================================================================
#define BUFB (4 * ABYTES)              // 16384 B per chunk buffer

__global__ __launch_bounds__(256, 2) void gemm_out(
    const __nv_bfloat16* __restrict__ AH, const __nv_bfloat16* __restrict__ AL,
    const __nv_bfloat16* __restrict__ BHg, const __nv_bfloat16* __restrict__ BLg,
    const float* __restrict__ bias, float* __restrict__ Out)
{
    __shared__ __nv_bfloat16 smem[3 * BUFB / 2];   // 48 KB

    const int tid = threadIdx.x;
    const int wid = tid >> 5, lane = tid & 31;
    const int g = lane >> 2, tig = lane & 3;
    const int m0 = blockIdx.y * 128;
    const int n0 = blockIdx.x * 128;
    const int wm = (wid & 1) * 64;
    const int wn = (wid >> 1) * 32;
    const int bb = m0 >> 13;

    const __nv_bfloat16* BH = BHg + (size_t)bb * 262144;
    const __nv_bfloat16* BL = BLg + (size_t)bb * 262144;

    const int frow = tid >> 1, fj = tid & 1;
    const int fslot = fj ^ ((frow >> 2) & 1);
    const uint32_t sOff = (uint32_t)(frow * 32 + fslot * 16);
    const __nv_bfloat16* gah = AH + (size_t)(m0 + frow) * 512 + fj * 8;
    const __nv_bfloat16* gal = AL + (size_t)(m0 + frow) * 512 + fj * 8;
    const __nv_bfloat16* gbh = BH + (size_t)(n0 + frow) * 512 + fj * 8;
    const __nv_bfloat16* gbl = BL + (size_t)(n0 + frow) * 512 + fj * 8;

    const uint32_t sBase = smem_u32(smem);

    const int ar = lane & 15, akh = lane >> 4;
    const uint32_t aoff =
        (uint32_t)((wm + ar) * 32 + ((akh ^ ((ar >> 2) & 1)) * 16));
    const int brl = ((lane >> 4) & 1) * 8 + (lane & 7);
    const int bkh = (lane >> 3) & 1;
    const uint32_t boff =
        (uint32_t)((wn + brl) * 32 + ((bkh ^ (((lane & 7) >> 2) & 1)) * 16));

    auto issue = [&](int k0, int bufI) {
        const uint32_t nb = sBase + (uint32_t)(bufI * BUFB);
        cp16(nb + 0 * ABYTES + sOff, gah + k0);
        cp16(nb + 1 * ABYTES + sOff, gal + k0);
        cp16(nb + 2 * ABYTES + sOff, gbh + k0);
        cp16(nb + 3 * ABYTES + sOff, gbl + k0);
        asm volatile("cp.async.commit_group;" ::: "memory");
    };

    float acc[4][4][4];
#pragma unroll
    for (int i = 0; i < 4; i++)
#pragma unroll
        for (int j = 0; j < 4; j++)
#pragma unroll
            for (int t = 0; t < 4; t++) acc[i][j][t] = 0.f;

    issue(0, 0);
    issue(16, 1);

    for (int kc = 0; kc < 32; kc++) {
        if (kc < 31) {
            asm volatile("cp.async.wait_group 1;" ::: "memory");
        } else {
            asm volatile("cp.async.wait_group 0;" ::: "memory");
        }
        __syncthreads();

        if (kc < 30) issue((kc + 2) * 16, (kc + 2) % 3);

        const uint32_t cb = sBase + (uint32_t)((kc % 3) * BUFB);
        const uint32_t aBaseH = cb + aoff;
        const uint32_t aBaseL = cb + ABYTES + aoff;
        const uint32_t bBaseH = cb + 2 * ABYTES + boff;
        const uint32_t bBaseL = cb + 3 * ABYTES + boff;

        uint32_t ah[4][4], al[4][4];
#pragma unroll
        for (int mt = 0; mt < 4; mt++) {
            const uint32_t ro = (uint32_t)(mt * 512);
            ldsm4(ah[mt], aBaseH + ro);
            ldsm4(al[mt], aBaseL + ro);
        }
#pragma unroll
        for (int ntp = 0; ntp < 2; ntp++) {
            const uint32_t ro = (uint32_t)(ntp * 512);
            uint32_t bh4[4], bl4[4];
            ldsm4(bh4, bBaseH + ro);
            ldsm4(bl4, bBaseL + ro);
#pragma unroll
            for (int half = 0; half < 2; half++) {
                const int nt = ntp * 2 + half;
                const uint32_t* bh = bh4 + half * 2;
                const uint32_t* bl = bl4 + half * 2;
#pragma unroll
                for (int mt = 0; mt < 4; mt++) {
                    mma16816(acc[mt][nt], ah[mt], bh);
                    mma16816(acc[mt][nt], ah[mt], bl);
                    mma16816(acc[mt][nt], al[mt], bh);
                }
            }
        }
    }

    {
        const int cb2 = n0 + wn;
#pragma unroll
        for (int mt = 0; mt < 4; mt++) {
            int r0 = m0 + wm + mt * 16 + g;
#pragma unroll
            for (int nt = 0; nt < 4; nt++) {
                int c = cb2 + nt * 8 + tig * 2;
                float b0 = bias[c], b1 = bias[c + 1];
                *(float2*)&Out[(size_t)r0 * 512 + c] =
                    make_float2(acc[mt][nt][0] + b0, acc[mt][nt][1] + b1);
                *(float2*)&Out[(size_t)(r0 + 8) * 512 + c] =
                    make_float2(acc[mt][nt][2] + b0, acc[mt][nt][3] + b1);
            }
        }
    }
}

// ============================================================================
// kv partial reduce + combine (fp32 SIMT) [R1/R5-verified]
// ============================================================================
__global__ __launch_bounds__(256, 4) void kv_reduce()
{
    __shared__ float ks[8][64];
    __shared__ float vs[8][64];
    const int bh = blockIdx.x;
    const int b = bh >> 3, h = bh & 7;
    const int nbase = blockIdx.y * 512;
    const int tid = threadIdx.x;
    const int tx = tid & 15, ty = tid >> 4;

    float acc[4][4];
#pragma unroll
    for (int i = 0; i < 4; i++)
#pragma unroll
        for (int j = 0; j < 4; j++) acc[i][j] = 0.f;
    float ksacc[4] = {0.f, 0.f, 0.f, 0.f};

    const int lr = (tid & 127) >> 4;
    const int lc = tid & 15;
    const float* src = (tid < 128) ? g_k : g_v;
    float* sdst = (tid < 128) ? &ks[lr][lc * 4] : &vs[lr][lc * 4];

    for (int r0 = 0; r0 < 512; r0 += 8) {
        int n = nbase + r0 + lr;
        float4 val = *(const float4*)&src[((size_t)(b * 8192 + n)) * 512 + h * 64 + lc * 4];
        *(float4*)sdst = val;
        __syncthreads();
#pragma unroll
        for (int r = 0; r < 8; r++) {
            float kf[4], vf[4];
            *(float4*)kf = *(float4*)&ks[r][tx * 4];
            *(float4*)vf = *(float4*)&vs[r][ty * 4];
#pragma unroll
            for (int i = 0; i < 4; i++)
#pragma unroll
                for (int j = 0; j < 4; j++) acc[i][j] += kf[i] * vf[j];
            if (ty == 0) {
#pragma unroll
                for (int i = 0; i < 4; i++) ksacc[i] += kf[i];
            }
        }
        __syncthreads();
    }

    const size_t base = (size_t)(bh * 16 + blockIdx.y) * 4160;
#pragma unroll
    for (int i = 0; i < 4; i++)
#pragma unroll
        for (int j = 0; j < 4; j++)
            g_kvpart[base + (tx * 4 + i) * 64 + ty * 4 + j] = acc[i][j];
    if (ty == 0) {
#pragma unroll
        for (int i = 0; i < 4; i++) g_kvpart[base + 4096 + tx * 4 + i] = ksacc[i];
    }
}

__global__ void kv_combine()
{
    const int bh = blockIdx.x;
    const int i0 = blockIdx.y * 260;
    const int iend = (i0 + 260 < 4160) ? i0 + 260 : 4160;
    for (int i = i0 + threadIdx.x; i < iend; i += 256) {
        float s = 0.f;
#pragma unroll
        for (int c = 0; c < 16; c++) s += g_kvpart[(size_t)(bh * 16 + c) * 4160 + i];
        g_kv[(size_t)bh * 4160 + i] = s;
    }
}

// ============================================================================
// Wbig^T bf16 hi/lo  [R6-verified]
// ============================================================================
__global__ void make_wbig(const float* __restrict__ Wout)
{
    const int r = blockIdx.x;          // h*64+d
    const int b = blockIdx.y;
    const int h = r >> 6, d = r & 63;
    __shared__ float kvrow[64];
    if (threadIdx.x < 64)
        kvrow[threadIdx.x] = g_kv[(size_t)(b * 8 + h) * 4160 + d * 64 + threadIdx.x];
    __syncthreads();
    float acc[4] = {0.f, 0.f, 0.f, 0.f};
    for (int m = 0; m < 64; m++) {
        float kvv = kvrow[m];
        const float* wrow = Wout + (size_t)(h * 64 + m) * 512;
#pragma unroll
        for (int i = 0; i < 4; i++) acc[i] += kvv * wrow[threadIdx.x + i * 128];
    }
#pragma unroll
    for (int i = 0; i < 4; i++) {
        int j = threadIdx.x + i * 128;
        __nv_bfloat16 hi, lo;
        split2(acc[i], hi, lo);
        g_wbth[(size_t)b * 262144 + (size_t)j * 512 + r] = hi;
        g_wbtl[(size_t)b * 262144 + (size_t)j * 512 + r] = lo;
    }
}

// ============================================================================
extern "C" void kernel_launch(void* const* d_in, const int* in_sizes, int n_in,
                              void* d_out, int out_size)
{
    const float* x     = (const float*)d_in[0];   // [4,8192,512]
    const float* w_qkv = (const float*)d_in[1];   // [512,1536]
    const float* w_out = (const float*)d_in[2];   // [512,512]
    const float* b_out = (const float*)d_in[3];   // [512]
    float* out = (float*)d_out;                   // [4,8192,512]

    __half *xf_p, *wfh_p, *wfl_p;
    __nv_bfloat16 *qzh_p, *qzl_p, *wbth_p, *wbtl_p;
    cudaGetSymbolAddress((void**)&xf_p,  g_xf);
    cudaGetSymbolAddress((void**)&wfh_p, g_wfh);
    cudaGetSymbolAddress((void**)&wfl_p, g_wfl);
    cudaGetSymbolAddress((void**)&qzh_p, g_qzh);
    cudaGetSymbolAddress((void**)&qzl_p, g_qzl);
    cudaGetSymbolAddress((void**)&wbth_p, g_wbth);
    cudaGetSymbolAddress((void**)&wbtl_p, g_wbtl);

    transpose_w<<<dim3(48, 16), dim3(32, 8)>>>(w_qkv);
    conv_x_f16<<<16384, 256>>>(x);
    conv_w_f16<<<3072, 256>>>();
    gemm_f16<<<dim3(12, 256), 256>>>(xf_p, wfh_p, wfl_p);
    kv_reduce<<<dim3(32, 16), 256>>>();
    kv_combine<<<dim3(32, 16), 256>>>();
    make_wbig<<<dim3(512, 4), 128>>>(w_out);
    z_split<<<32768, 128>>>();
    gemm_out<<<dim3(4, 256), 256>>>(qzh_p, qzl_p, wbth_p, wbtl_p, b_out, out);
}

// round 13
// speedup vs baseline: 1.5788x; 1.1241x over previous
#include <cuda_runtime.h>
#include <cuda_bf16.h>
#include <cuda_fp16.h>
#include <math.h>
#include <stdint.h>

#define MROWS (4 * 8192)          // 32768 rows total
#define DIMK  512
#define NQKV  1536

// ---------------- scratch (device globals; no allocation allowed) ----------
__device__ float g_q[MROWS * 512];          // elu(q)+1 fp32
__device__ float g_k[MROWS * 512];          // elu(k)+1 fp32
__device__ float g_v[MROWS * 512];          // v fp32
__device__ float g_kvpart[32 * 16 * 4160];  // per (bh,chunk): 64x64 kv + 64 ksum
__device__ float g_kv[32 * 4160];
__device__ float g_wt[NQKV * 512];          // w_qkv^T fp32 [n][k]

__device__ __half g_xf[MROWS * 512];          // x single fp16
__device__ __half g_wfh[NQKV * 512];          // (16*w^T) hi fp16
__device__ __half g_wfl[NQKV * 512];          // (16*w^T) lo fp16
__device__ __half g_qzf[MROWS * 512];         // (q*z*2^15) single fp16
__device__ __half g_wbfh[4 * 512 * 512];      // Wbig^T hi fp16 [b][j][r]
__device__ __half g_wbfl[4 * 512 * 512];      // Wbig^T lo fp16

#define QZ_SCALE 32768.0f
#define QZ_INV   (1.0f / 32768.0f)

// ---------------- helpers ---------------------------------------------------
__device__ __forceinline__ void mma16816h(float* c, const uint32_t* a, const uint32_t* b) {
    asm volatile(
        "mma.sync.aligned.m16n8k16.row.col.f32.f16.f16.f32 "
        "{%0,%1,%2,%3}, {%4,%5,%6,%7}, {%8,%9}, {%0,%1,%2,%3};"
        : "+f"(c[0]), "+f"(c[1]), "+f"(c[2]), "+f"(c[3])
        : "r"(a[0]), "r"(a[1]), "r"(a[2]), "r"(a[3]), "r"(b[0]), "r"(b[1]));
}
__device__ __forceinline__ void ldsm4(uint32_t* r, uint32_t a) {
    asm volatile("ldmatrix.sync.aligned.m8n8.x4.shared.b16 {%0,%1,%2,%3}, [%4];"
        : "=r"(r[0]), "=r"(r[1]), "=r"(r[2]), "=r"(r[3]) : "r"(a));
}
__device__ __forceinline__ uint32_t smem_u32(const void* p) {
    uint32_t a;
    asm("{ .reg .u64 t; cvta.to.shared.u64 t, %1; cvt.u32.u64 %0, t; }" : "=r"(a) : "l"(p));
    return a;
}
__device__ __forceinline__ void cp16(uint32_t s, const void* g) {
    asm volatile("cp.async.cg.shared.global [%0], [%1], 16;" :: "r"(s), "l"(g));
}
__device__ __forceinline__ float elu1(float x) {
    return x >= 0.f ? x + 1.f : __expf(x);
}

// ============================================================================
// W transpose: g_wt[n][k] = W[k][n]   (W: [512][1536])   [R5-verified]
// ============================================================================
__global__ void transpose_w(const float* __restrict__ W)
{
    __shared__ float t[32][33];
    const int bx = blockIdx.x * 32;   // n base
    const int by = blockIdx.y * 32;   // k base
    const int x = threadIdx.x;
    for (int yy = threadIdx.y; yy < 32; yy += 8)
        t[yy][x] = W[(size_t)(by + yy) * NQKV + bx + x];
    __syncthreads();
    for (int yy = threadIdx.y; yy < 32; yy += 8)
        g_wt[(size_t)(bx + yy) * 512 + by + x] = t[x][yy];
}

// ============================================================================
// conv_x_f16: X fp32 -> single fp16 (same index)  [R12-verified]
// ============================================================================
__global__ void conv_x_f16(const float* __restrict__ X)
{
    size_t i4 = (size_t)blockIdx.x * 256 + threadIdx.x;
    float4 v = ((const float4*)X)[i4];
    __half2* O = (__half2*)g_xf;
    O[i4 * 2]     = __floats2half2_rn(v.x, v.y);
    O[i4 * 2 + 1] = __floats2half2_rn(v.z, v.w);
}

// ============================================================================
// conv_w_f16: g_wt fp32 -> fp16 hi/lo of (16*w)  (same index)  [R12-verified]
// ============================================================================
__global__ void conv_w_f16()
{
    size_t i = (size_t)blockIdx.x * 256 + threadIdx.x;
    float v = g_wt[i] * 16.0f;
    __half hi = __float2half_rn(v);
    __half lo = __float2half_rn(v - __half2float(hi));
    g_wfh[i] = hi;
    g_wfl[i] = lo;
}

// ============================================================================
// z_split: fused compute_z + qz conversion -> single fp16 of (q*z*2^15)
// (dot/shfl structure R8-verified; output format changed)
// ============================================================================
__global__ __launch_bounds__(128) void z_split()
{
    const int row = blockIdx.x;            // 0..32767
    const int b = row >> 13;
    const int t = threadIdx.x;             // 0..127
    const int h = t >> 4;
    const int e = t * 4;
    const int d = e & 63;

    float4 q = *(const float4*)(g_q + (size_t)row * 512 + e);
    const float* ks = g_kv + (size_t)(b * 8 + h) * 4160 + 4096 + d;
    float part = q.x * ks[0] + q.y * ks[1] + q.z * ks[2] + q.w * ks[3];
#pragma unroll
    for (int off = 8; off; off >>= 1)
        part += __shfl_xor_sync(0xFFFFFFFFu, part, off);
    const float zs = QZ_SCALE / (part + 1e-6f);

    __half2* O = (__half2*)g_qzf;
    size_t o2 = ((size_t)row * 512 + e) >> 1;
    O[o2]     = __floats2half2_rn(q.x * zs, q.y * zs);
    O[o2 + 1] = __floats2half2_rn(q.z * zs, q.w * zs);
}

// ============================================================================
// fp16 2-product GEMM [R12-verified skeleton]: C = A @ (Bh+Bl).
// A single fp16, B split fp16. C tile 128x128, K=512 in 32 chunks of 16.
// XOR-swizzled 32B rows; chunk buffer = 3 arrays x 4096B = 12KB; 4 buffers =
// 48KB static smem; 4-stage cp.async pipeline.
// MODE 0: A=x, B=16*Wqkv^T -> q/k/v fp32 with elu+1 on q,k (scale 1/16)
// MODE 1: A=qz*2^15, B=Wbig^T[b] -> Out = C*2^-15 + bias
// ============================================================================
#define ABYTES 4096                    // one array: 128 rows x 32 B
#define BUF0B (3 * ABYTES)             // 12288 B per chunk buffer

template <int MODE>
__global__ __launch_bounds__(256, 2) void gemm_f16(
    const __half* __restrict__ Ag, const __half* __restrict__ BHg,
    const __half* __restrict__ BLg,
    const float* __restrict__ bias, float* __restrict__ Out)
{
    __shared__ __half smem[4 * BUF0B / 2];   // 48 KB

    const int tid = threadIdx.x;
    const int wid = tid >> 5, lane = tid & 31;
    const int g = lane >> 2, tig = lane & 3;
    const int m0 = blockIdx.y * 128;
    const int n0 = blockIdx.x * 128;
    const int wm = (wid & 1) * 64;
    const int wn = (wid >> 1) * 32;
    const int bb = m0 >> 13;          // batch (tiles never straddle batches)

    const __half* BH = BHg + (MODE == 1 ? (size_t)bb * 262144 : 0);
    const __half* BL = BLg + (MODE == 1 ? (size_t)bb * 262144 : 0);

    // fill mapping: thread t -> row = t>>1, k8-group j = t&1, swizzled slot
    const int frow = tid >> 1, fj = tid & 1;
    const int fslot = fj ^ ((frow >> 2) & 1);
    const uint32_t sOff = (uint32_t)(frow * 32 + fslot * 16);
    const __half* ga  = Ag + (size_t)(m0 + frow) * 512 + fj * 8;
    const __half* gbh = BH + (size_t)(n0 + frow) * 512 + fj * 8;
    const __half* gbl = BL + (size_t)(n0 + frow) * 512 + fj * 8;

    const uint32_t sBase = smem_u32(smem);

    // ldmatrix per-lane offsets [R11-verified swizzle]
    const int ar = lane & 15, akh = lane >> 4;
    const uint32_t aoff =
        (uint32_t)((wm + ar) * 32 + ((akh ^ ((ar >> 2) & 1)) * 16));
    const int brl = ((lane >> 4) & 1) * 8 + (lane & 7);
    const int bkh = (lane >> 3) & 1;
    const uint32_t boff =
        (uint32_t)((wn + brl) * 32 + ((bkh ^ (((lane & 7) >> 2) & 1)) * 16));

    auto issue = [&](int k0, int bufI) {
        const uint32_t nb = sBase + (uint32_t)(bufI * BUF0B);
        cp16(nb + 0 * ABYTES + sOff, ga + k0);
        cp16(nb + 1 * ABYTES + sOff, gbh + k0);
        cp16(nb + 2 * ABYTES + sOff, gbl + k0);
        asm volatile("cp.async.commit_group;" ::: "memory");
    };

    float acc[4][4][4];
#pragma unroll
    for (int i = 0; i < 4; i++)
#pragma unroll
        for (int j = 0; j < 4; j++)
#pragma unroll
            for (int t = 0; t < 4; t++) acc[i][j][t] = 0.f;

    // ---- prologue: chunks 0,1,2 into buffers 0,1,2 ----
    issue(0, 0);
    issue(16, 1);
    issue(32, 2);

    for (int kc = 0; kc < 32; kc++) {
        if (kc < 30) {
            asm volatile("cp.async.wait_group 2;" ::: "memory");
        } else if (kc == 30) {
            asm volatile("cp.async.wait_group 1;" ::: "memory");
        } else {
            asm volatile("cp.async.wait_group 0;" ::: "memory");
        }
        __syncthreads();   // chunk kc visible; all warps done with buf (kc+3)&3

        if (kc <= 28) issue((kc + 3) * 16, (kc + 3) & 3);

        const uint32_t cb = sBase + (uint32_t)((kc & 3) * BUF0B);
        const uint32_t aBase  = cb + aoff;
        const uint32_t bBaseH = cb + 1 * ABYTES + boff;
        const uint32_t bBaseL = cb + 2 * ABYTES + boff;

        uint32_t a4[4][4];
#pragma unroll
        for (int mt = 0; mt < 4; mt++)
            ldsm4(a4[mt], aBase + (uint32_t)(mt * 512));
#pragma unroll
        for (int ntp = 0; ntp < 2; ntp++) {
            const uint32_t ro = (uint32_t)(ntp * 512);
            uint32_t bh4[4], bl4[4];
            ldsm4(bh4, bBaseH + ro);
            ldsm4(bl4, bBaseL + ro);
#pragma unroll
            for (int half = 0; half < 2; half++) {
                const int nt = ntp * 2 + half;
                const uint32_t* bh = bh4 + half * 2;
                const uint32_t* bl = bl4 + half * 2;
#pragma unroll
                for (int mt = 0; mt < 4; mt++) {
                    mma16816h(acc[mt][nt], a4[mt], bl);
                    mma16816h(acc[mt][nt], a4[mt], bh);
                }
            }
        }
    }

    // -------- epilogue --------
    if (MODE == 0) {
        float* dst = (n0 < 512) ? g_q : (n0 < 1024 ? g_k : g_v);
        const bool act = (n0 < 1024);
        const int cb2 = (n0 & 511) + wn;
        const float sc = 1.0f / 16.0f;
#pragma unroll
        for (int mt = 0; mt < 4; mt++) {
            int r0 = m0 + wm + mt * 16 + g;
#pragma unroll
            for (int nt = 0; nt < 4; nt++) {
                int c = cb2 + nt * 8 + tig * 2;
                float v0 = acc[mt][nt][0] * sc, v1 = acc[mt][nt][1] * sc;
                float v2 = acc[mt][nt][2] * sc, v3 = acc[mt][nt][3] * sc;
                if (act) { v0 = elu1(v0); v1 = elu1(v1); v2 = elu1(v2); v3 = elu1(v3); }
                *(float2*)&dst[(size_t)r0 * 512 + c]       = make_float2(v0, v1);
                *(float2*)&dst[(size_t)(r0 + 8) * 512 + c] = make_float2(v2, v3);
            }
        }
    } else {
        const int cb2 = n0 + wn;
#pragma unroll
        for (int mt = 0; mt < 4; mt++) {
            int r0 = m0 + wm + mt * 16 + g;
#pragma unroll
            for (int nt = 0; nt < 4; nt++) {
                int c = cb2 + nt * 8 + tig * 2;
                float b0 = bias[c], b1 = bias[c + 1];
                *(float2*)&Out[(size_t)r0 * 512 + c] =
                    make_float2(acc[mt][nt][0] * QZ_INV + b0,
                                acc[mt][nt][1] * QZ_INV + b1);
                *(float2*)&Out[(size_t)(r0 + 8) * 512 + c] =
                    make_float2(acc[mt][nt][2] * QZ_INV + b0,
                                acc[mt][nt][3] * QZ_INV + b1);
            }
        }
    }
}

// ============================================================================
// kv partial reduce + combine (fp32 SIMT) [R1/R5-verified]
// ============================================================================
__global__ __launch_bounds__(256, 4) void kv_reduce()
{
    __shared__ float ks[8][64];
    __shared__ float vs[8][64];
    const int bh = blockIdx.x;
    const int b = bh >> 3, h = bh & 7;
    const int nbase = blockIdx.y * 512;
    const int tid = threadIdx.x;
    const int tx = tid & 15, ty = tid >> 4;

    float acc[4][4];
#pragma unroll
    for (int i = 0; i < 4; i++)
#pragma unroll
        for (int j = 0; j < 4; j++) acc[i][j] = 0.f;
    float ksacc[4] = {0.f, 0.f, 0.f, 0.f};

    const int lr = (tid & 127) >> 4;
    const int lc = tid & 15;
    const float* src = (tid < 128) ? g_k : g_v;
    float* sdst = (tid < 128) ? &ks[lr][lc * 4] : &vs[lr][lc * 4];

    for (int r0 = 0; r0 < 512; r0 += 8) {
        int n = nbase + r0 + lr;
        float4 val = *(const float4*)&src[((size_t)(b * 8192 + n)) * 512 + h * 64 + lc * 4];
        *(float4*)sdst = val;
        __syncthreads();
#pragma unroll
        for (int r = 0; r < 8; r++) {
            float kf[4], vf[4];
            *(float4*)kf = *(float4*)&ks[r][tx * 4];
            *(float4*)vf = *(float4*)&vs[r][ty * 4];
#pragma unroll
            for (int i = 0; i < 4; i++)
#pragma unroll
                for (int j = 0; j < 4; j++) acc[i][j] += kf[i] * vf[j];
            if (ty == 0) {
#pragma unroll
                for (int i = 0; i < 4; i++) ksacc[i] += kf[i];
            }
        }
        __syncthreads();
    }

    const size_t base = (size_t)(bh * 16 + blockIdx.y) * 4160;
#pragma unroll
    for (int i = 0; i < 4; i++)
#pragma unroll
        for (int j = 0; j < 4; j++)
            g_kvpart[base + (tx * 4 + i) * 64 + ty * 4 + j] = acc[i][j];
    if (ty == 0) {
#pragma unroll
        for (int i = 0; i < 4; i++) g_kvpart[base + 4096 + tx * 4 + i] = ksacc[i];
    }
}

__global__ void kv_combine()
{
    const int bh = blockIdx.x;
    const int i0 = blockIdx.y * 260;
    const int iend = (i0 + 260 < 4160) ? i0 + 260 : 4160;
    for (int i = i0 + threadIdx.x; i < iend; i += 256) {
        float s = 0.f;
#pragma unroll
        for (int c = 0; c < 16; c++) s += g_kvpart[(size_t)(bh * 16 + c) * 4160 + i];
        g_kv[(size_t)bh * 4160 + i] = s;
    }
}

// ============================================================================
// Wbig^T fp16 hi/lo: [b][j][r] = sum_m kv[b,h,d,m] * w_out[h*64+m][j]
// (R6-verified compute; store format fp16 hi/lo)
// ============================================================================
__global__ void make_wbig(const float* __restrict__ Wout)
{
    const int r = blockIdx.x;          // h*64+d
    const int b = blockIdx.y;
    const int h = r >> 6, d = r & 63;
    __shared__ float kvrow[64];
    if (threadIdx.x < 64)
        kvrow[threadIdx.x] = g_kv[(size_t)(b * 8 + h) * 4160 + d * 64 + threadIdx.x];
    __syncthreads();
    float acc[4] = {0.f, 0.f, 0.f, 0.f};
    for (int m = 0; m < 64; m++) {
        float kvv = kvrow[m];
        const float* wrow = Wout + (size_t)(h * 64 + m) * 512;
#pragma unroll
        for (int i = 0; i < 4; i++) acc[i] += kvv * wrow[threadIdx.x + i * 128];
    }
#pragma unroll
    for (int i = 0; i < 4; i++) {
        int j = threadIdx.x + i * 128;
        __half hi = __float2half_rn(acc[i]);
        __half lo = __float2half_rn(acc[i] - __half2float(hi));
        g_wbfh[(size_t)b * 262144 + (size_t)j * 512 + r] = hi;
        g_wbfl[(size_t)b * 262144 + (size_t)j * 512 + r] = lo;
    }
}

// ============================================================================
extern "C" void kernel_launch(void* const* d_in, const int* in_sizes, int n_in,
                              void* d_out, int out_size)
{
    const float* x     = (const float*)d_in[0];   // [4,8192,512]
    const float* w_qkv = (const float*)d_in[1];   // [512,1536]
    const float* w_out = (const float*)d_in[2];   // [512,512]
    const float* b_out = (const float*)d_in[3];   // [512]
    float* out = (float*)d_out;                   // [4,8192,512]

    __half *xf_p, *wfh_p, *wfl_p, *qzf_p, *wbfh_p, *wbfl_p;
    cudaGetSymbolAddress((void**)&xf_p,  g_xf);
    cudaGetSymbolAddress((void**)&wfh_p, g_wfh);
    cudaGetSymbolAddress((void**)&wfl_p, g_wfl);
    cudaGetSymbolAddress((void**)&qzf_p, g_qzf);
    cudaGetSymbolAddress((void**)&wbfh_p, g_wbfh);
    cudaGetSymbolAddress((void**)&wbfl_p, g_wbfl);

    transpose_w<<<dim3(48, 16), dim3(32, 8)>>>(w_qkv);
    conv_x_f16<<<16384, 256>>>(x);
    conv_w_f16<<<3072, 256>>>();
    gemm_f16<0><<<dim3(12, 256), 256>>>(xf_p, wfh_p, wfl_p, nullptr, nullptr);
    kv_reduce<<<dim3(32, 16), 256>>>();
    kv_combine<<<dim3(32, 16), 256>>>();
    make_wbig<<<dim3(512, 4), 128>>>(w_out);
    z_split<<<32768, 128>>>();
    gemm_f16<1><<<dim3(4, 256), 256>>>(qzf_p, wbfh_p, wbfl_p, b_out, out);
}

// round 14
// speedup vs baseline: 2.1081x; 1.3353x over previous
#include <cuda_runtime.h>
#include <cuda_bf16.h>
#include <cuda_fp16.h>
#include <math.h>
#include <stdint.h>

#define MROWS (4 * 8192)          // 32768 rows total
#define DIMK  512
#define NQKV  1536

// ---------------- scratch (device globals; no allocation allowed) ----------
__device__ float g_q[MROWS * 512];          // elu(q)+1 fp32
__device__ float g_k[MROWS * 512];          // elu(k)+1 fp32
__device__ float g_v[MROWS * 512];          // v fp32
__device__ float g_kvpart[32 * 16 * 4160];  // per (bh,chunk): 64x64 kv + 64 ksum
__device__ float g_kv[32 * 4160];
__device__ float g_wt[NQKV * 512];          // w_qkv^T fp32 [n][k]

__device__ __half g_xf[MROWS * 512];        // x single fp16
__device__ __half g_wf[NQKV * 512];         // w^T single fp16
__device__ __half g_qzf[MROWS * 512];       // (q*z*2^15) single fp16
__device__ __half g_wbf[4 * 512 * 512];     // Wbig^T single fp16 [b][j][r]

#define QZ_SCALE 32768.0f
#define QZ_INV   (1.0f / 32768.0f)

// ---------------- helpers ---------------------------------------------------
__device__ __forceinline__ void mma16816h(float* c, const uint32_t* a, const uint32_t* b) {
    asm volatile(
        "mma.sync.aligned.m16n8k16.row.col.f32.f16.f16.f32 "
        "{%0,%1,%2,%3}, {%4,%5,%6,%7}, {%8,%9}, {%0,%1,%2,%3};"
        : "+f"(c[0]), "+f"(c[1]), "+f"(c[2]), "+f"(c[3])
        : "r"(a[0]), "r"(a[1]), "r"(a[2]), "r"(a[3]), "r"(b[0]), "r"(b[1]));
}
__device__ __forceinline__ void ldsm4(uint32_t* r, uint32_t a) {
    asm volatile("ldmatrix.sync.aligned.m8n8.x4.shared.b16 {%0,%1,%2,%3}, [%4];"
        : "=r"(r[0]), "=r"(r[1]), "=r"(r[2]), "=r"(r[3]) : "r"(a));
}
__device__ __forceinline__ uint32_t smem_u32(const void* p) {
    uint32_t a;
    asm("{ .reg .u64 t; cvta.to.shared.u64 t, %1; cvt.u32.u64 %0, t; }" : "=r"(a) : "l"(p));
    return a;
}
__device__ __forceinline__ void cp16(uint32_t s, const void* g) {
    asm volatile("cp.async.cg.shared.global [%0], [%1], 16;" :: "r"(s), "l"(g));
}
__device__ __forceinline__ float elu1(float x) {
    return x >= 0.f ? x + 1.f : __expf(x);
}

// ============================================================================
// W transpose: g_wt[n][k] = W[k][n]   (W: [512][1536])   [R5-verified]
// ============================================================================
__global__ void transpose_w(const float* __restrict__ W)
{
    __shared__ float t[32][33];
    const int bx = blockIdx.x * 32;   // n base
    const int by = blockIdx.y * 32;   // k base
    const int x = threadIdx.x;
    for (int yy = threadIdx.y; yy < 32; yy += 8)
        t[yy][x] = W[(size_t)(by + yy) * NQKV + bx + x];
    __syncthreads();
    for (int yy = threadIdx.y; yy < 32; yy += 8)
        g_wt[(size_t)(bx + yy) * 512 + by + x] = t[x][yy];
}

// ============================================================================
// conv_x_f16: X fp32 -> single fp16 (same index)  [R12-verified]
// ============================================================================
__global__ void conv_x_f16(const float* __restrict__ X)
{
    size_t i4 = (size_t)blockIdx.x * 256 + threadIdx.x;
    float4 v = ((const float4*)X)[i4];
    __half2* O = (__half2*)g_xf;
    O[i4 * 2]     = __floats2half2_rn(v.x, v.y);
    O[i4 * 2 + 1] = __floats2half2_rn(v.z, v.w);
}

// ============================================================================
// conv_w_f16: g_wt fp32 -> single fp16 (same index)
// ============================================================================
__global__ void conv_w_f16()
{
    size_t i = (size_t)blockIdx.x * 256 + threadIdx.x;
    g_wf[i] = __float2half_rn(g_wt[i]);
}

// ============================================================================
// z_split: fused compute_z + qz conversion -> single fp16 of (q*z*2^15)
// [R13-verified]
// ============================================================================
__global__ __launch_bounds__(128) void z_split()
{
    const int row = blockIdx.x;            // 0..32767
    const int b = row >> 13;
    const int t = threadIdx.x;             // 0..127
    const int h = t >> 4;
    const int e = t * 4;
    const int d = e & 63;

    float4 q = *(const float4*)(g_q + (size_t)row * 512 + e);
    const float* ks = g_kv + (size_t)(b * 8 + h) * 4160 + 4096 + d;
    float part = q.x * ks[0] + q.y * ks[1] + q.z * ks[2] + q.w * ks[3];
#pragma unroll
    for (int off = 8; off; off >>= 1)
        part += __shfl_xor_sync(0xFFFFFFFFu, part, off);
    const float zs = QZ_SCALE / (part + 1e-6f);

    __half2* O = (__half2*)g_qzf;
    size_t o2 = ((size_t)row * 512 + e) >> 1;
    O[o2]     = __floats2half2_rn(q.x * zs, q.y * zs);
    O[o2 + 1] = __floats2half2_rn(q.z * zs, q.w * zs);
}

// ============================================================================
// fp16 single-product GEMM [R12/R13-verified skeleton, BL deleted]:
// C = A @ B. C tile 128x128, K=512 in 32 chunks of 16. XOR-swizzled 32B rows;
// chunk buffer = 2 arrays x 4096B = 8KB; 4 buffers = 32KB static smem;
// 4-stage cp.async pipeline.
// MODE 0: A=x, B=Wqkv^T -> q/k/v fp32 with elu+1 on q,k
// MODE 1: A=qz*2^15, B=Wbig^T[b] -> Out = C*2^-15 + bias
// ============================================================================
#define ABYTES 4096                    // one array: 128 rows x 32 B
#define BUF0B (2 * ABYTES)             // 8192 B per chunk buffer

template <int MODE>
__global__ __launch_bounds__(256, 2) void gemm_f16(
    const __half* __restrict__ Ag, const __half* __restrict__ Bg,
    const float* __restrict__ bias, float* __restrict__ Out)
{
    __shared__ __half smem[4 * BUF0B / 2];   // 32 KB

    const int tid = threadIdx.x;
    const int wid = tid >> 5, lane = tid & 31;
    const int g = lane >> 2, tig = lane & 3;
    const int m0 = blockIdx.y * 128;
    const int n0 = blockIdx.x * 128;
    const int wm = (wid & 1) * 64;
    const int wn = (wid >> 1) * 32;
    const int bb = m0 >> 13;          // batch (tiles never straddle batches)

    const __half* B = Bg + (MODE == 1 ? (size_t)bb * 262144 : 0);

    // fill mapping: thread t -> row = t>>1, k8-group j = t&1, swizzled slot
    const int frow = tid >> 1, fj = tid & 1;
    const int fslot = fj ^ ((frow >> 2) & 1);
    const uint32_t sOff = (uint32_t)(frow * 32 + fslot * 16);
    const __half* ga = Ag + (size_t)(m0 + frow) * 512 + fj * 8;
    const __half* gb = B  + (size_t)(n0 + frow) * 512 + fj * 8;

    const uint32_t sBase = smem_u32(smem);

    // ldmatrix per-lane offsets [R11-verified swizzle]
    const int ar = lane & 15, akh = lane >> 4;
    const uint32_t aoff =
        (uint32_t)((wm + ar) * 32 + ((akh ^ ((ar >> 2) & 1)) * 16));
    const int brl = ((lane >> 4) & 1) * 8 + (lane & 7);
    const int bkh = (lane >> 3) & 1;
    const uint32_t boff =
        (uint32_t)((wn + brl) * 32 + ((bkh ^ (((lane & 7) >> 2) & 1)) * 16));

    auto issue = [&](int k0, int bufI) {
        const uint32_t nb = sBase + (uint32_t)(bufI * BUF0B);
        cp16(nb + 0 * ABYTES + sOff, ga + k0);
        cp16(nb + 1 * ABYTES + sOff, gb + k0);
        asm volatile("cp.async.commit_group;" ::: "memory");
    };

    float acc[4][4][4];
#pragma unroll
    for (int i = 0; i < 4; i++)
#pragma unroll
        for (int j = 0; j < 4; j++)
#pragma unroll
            for (int t = 0; t < 4; t++) acc[i][j][t] = 0.f;

    // ---- prologue: chunks 0,1,2 into buffers 0,1,2 ----
    issue(0, 0);
    issue(16, 1);
    issue(32, 2);

    for (int kc = 0; kc < 32; kc++) {
        if (kc < 30) {
            asm volatile("cp.async.wait_group 2;" ::: "memory");
        } else if (kc == 30) {
            asm volatile("cp.async.wait_group 1;" ::: "memory");
        } else {
            asm volatile("cp.async.wait_group 0;" ::: "memory");
        }
        __syncthreads();   // chunk kc visible; all warps done with buf (kc+3)&3

        if (kc <= 28) issue((kc + 3) * 16, (kc + 3) & 3);

        const uint32_t cb = sBase + (uint32_t)((kc & 3) * BUF0B);
        const uint32_t aBase = cb + aoff;
        const uint32_t bBase = cb + ABYTES + boff;

        uint32_t a4[4][4];
#pragma unroll
        for (int mt = 0; mt < 4; mt++)
            ldsm4(a4[mt], aBase + (uint32_t)(mt * 512));
#pragma unroll
        for (int ntp = 0; ntp < 2; ntp++) {
            uint32_t b4[4];
            ldsm4(b4, bBase + (uint32_t)(ntp * 512));
#pragma unroll
            for (int half = 0; half < 2; half++) {
                const int nt = ntp * 2 + half;
                const uint32_t* bfrag = b4 + half * 2;
#pragma unroll
                for (int mt = 0; mt < 4; mt++)
                    mma16816h(acc[mt][nt], a4[mt], bfrag);
            }
        }
    }

    // -------- epilogue --------
    if (MODE == 0) {
        float* dst = (n0 < 512) ? g_q : (n0 < 1024 ? g_k : g_v);
        const bool act = (n0 < 1024);
        const int cb2 = (n0 & 511) + wn;
#pragma unroll
        for (int mt = 0; mt < 4; mt++) {
            int r0 = m0 + wm + mt * 16 + g;
#pragma unroll
            for (int nt = 0; nt < 4; nt++) {
                int c = cb2 + nt * 8 + tig * 2;
                float v0 = acc[mt][nt][0], v1 = acc[mt][nt][1];
                float v2 = acc[mt][nt][2], v3 = acc[mt][nt][3];
                if (act) { v0 = elu1(v0); v1 = elu1(v1); v2 = elu1(v2); v3 = elu1(v3); }
                *(float2*)&dst[(size_t)r0 * 512 + c]       = make_float2(v0, v1);
                *(float2*)&dst[(size_t)(r0 + 8) * 512 + c] = make_float2(v2, v3);
            }
        }
    } else {
        const int cb2 = n0 + wn;
#pragma unroll
        for (int mt = 0; mt < 4; mt++) {
            int r0 = m0 + wm + mt * 16 + g;
#pragma unroll
            for (int nt = 0; nt < 4; nt++) {
                int c = cb2 + nt * 8 + tig * 2;
                float b0 = bias[c], b1 = bias[c + 1];
                *(float2*)&Out[(size_t)r0 * 512 + c] =
                    make_float2(acc[mt][nt][0] * QZ_INV + b0,
                                acc[mt][nt][1] * QZ_INV + b1);
                *(float2*)&Out[(size_t)(r0 + 8) * 512 + c] =
                    make_float2(acc[mt][nt][2] * QZ_INV + b0,
                                acc[mt][nt][3] * QZ_INV + b1);
            }
        }
    }
}

// ============================================================================
// kv partial reduce + combine (fp32 SIMT) [R1/R5-verified]
// ============================================================================
__global__ __launch_bounds__(256, 4) void kv_reduce()
{
    __shared__ float ks[8][64];
    __shared__ float vs[8][64];
    const int bh = blockIdx.x;
    const int b = bh >> 3, h = bh & 7;
    const int nbase = blockIdx.y * 512;
    const int tid = threadIdx.x;
    const int tx = tid & 15, ty = tid >> 4;

    float acc[4][4];
#pragma unroll
    for (int i = 0; i < 4; i++)
#pragma unroll
        for (int j = 0; j < 4; j++) acc[i][j] = 0.f;
    float ksacc[4] = {0.f, 0.f, 0.f, 0.f};

    const int lr = (tid & 127) >> 4;
    const int lc = tid & 15;
    const float* src = (tid < 128) ? g_k : g_v;
    float* sdst = (tid < 128) ? &ks[lr][lc * 4] : &vs[lr][lc * 4];

    for (int r0 = 0; r0 < 512; r0 += 8) {
        int n = nbase + r0 + lr;
        float4 val = *(const float4*)&src[((size_t)(b * 8192 + n)) * 512 + h * 64 + lc * 4];
        *(float4*)sdst = val;
        __syncthreads();
#pragma unroll
        for (int r = 0; r < 8; r++) {
            float kf[4], vf[4];
            *(float4*)kf = *(float4*)&ks[r][tx * 4];
            *(float4*)vf = *(float4*)&vs[r][ty * 4];
#pragma unroll
            for (int i = 0; i < 4; i++)
#pragma unroll
                for (int j = 0; j < 4; j++) acc[i][j] += kf[i] * vf[j];
            if (ty == 0) {
#pragma unroll
                for (int i = 0; i < 4; i++) ksacc[i] += kf[i];
            }
        }
        __syncthreads();
    }

    const size_t base = (size_t)(bh * 16 + blockIdx.y) * 4160;
#pragma unroll
    for (int i = 0; i < 4; i++)
#pragma unroll
        for (int j = 0; j < 4; j++)
            g_kvpart[base + (tx * 4 + i) * 64 + ty * 4 + j] = acc[i][j];
    if (ty == 0) {
#pragma unroll
        for (int i = 0; i < 4; i++) g_kvpart[base + 4096 + tx * 4 + i] = ksacc[i];
    }
}

__global__ void kv_combine()
{
    const int bh = blockIdx.x;
    const int i0 = blockIdx.y * 260;
    const int iend = (i0 + 260 < 4160) ? i0 + 260 : 4160;
    for (int i = i0 + threadIdx.x; i < iend; i += 256) {
        float s = 0.f;
#pragma unroll
        for (int c = 0; c < 16; c++) s += g_kvpart[(size_t)(bh * 16 + c) * 4160 + i];
        g_kv[(size_t)bh * 4160 + i] = s;
    }
}

// ============================================================================
// Wbig^T single fp16: [b][j][r] = sum_m kv[b,h,d,m] * w_out[h*64+m][j]
// (R6-verified compute; store single fp16)
// ============================================================================
__global__ void make_wbig(const float* __restrict__ Wout)
{
    const int r = blockIdx.x;          // h*64+d
    const int b = blockIdx.y;
    const int h = r >> 6, d = r & 63;
    __shared__ float kvrow[64];
    if (threadIdx.x < 64)
        kvrow[threadIdx.x] = g_kv[(size_t)(b * 8 + h) * 4160 + d * 64 + threadIdx.x];
    __syncthreads();
    float acc[4] = {0.f, 0.f, 0.f, 0.f};
    for (int m = 0; m < 64; m++) {
        float kvv = kvrow[m];
        const float* wrow = Wout + (size_t)(h * 64 + m) * 512;
#pragma unroll
        for (int i = 0; i < 4; i++) acc[i] += kvv * wrow[threadIdx.x + i * 128];
    }
#pragma unroll
    for (int i = 0; i < 4; i++) {
        int j = threadIdx.x + i * 128;
        g_wbf[(size_t)b * 262144 + (size_t)j * 512 + r] = __float2half_rn(acc[i]);
    }
}

// ============================================================================
extern "C" void kernel_launch(void* const* d_in, const int* in_sizes, int n_in,
                              void* d_out, int out_size)
{
    const float* x     = (const float*)d_in[0];   // [4,8192,512]
    const float* w_qkv = (const float*)d_in[1];   // [512,1536]
    const float* w_out = (const float*)d_in[2];   // [512,512]
    const float* b_out = (const float*)d_in[3];   // [512]
    float* out = (float*)d_out;                   // [4,8192,512]

    __half *xf_p, *wf_p, *qzf_p, *wbf_p;
    cudaGetSymbolAddress((void**)&xf_p,  g_xf);
    cudaGetSymbolAddress((void**)&wf_p,  g_wf);
    cudaGetSymbolAddress((void**)&qzf_p, g_qzf);
    cudaGetSymbolAddress((void**)&wbf_p, g_wbf);

    transpose_w<<<dim3(48, 16), dim3(32, 8)>>>(w_qkv);
    conv_x_f16<<<16384, 256>>>(x);
    conv_w_f16<<<3072, 256>>>();
    gemm_f16<0><<<dim3(12, 256), 256>>>(xf_p, wf_p, nullptr, nullptr);
    kv_reduce<<<dim3(32, 16), 256>>>();
    kv_combine<<<dim3(32, 16), 256>>>();
    make_wbig<<<dim3(512, 4), 128>>>(w_out);
    z_split<<<32768, 128>>>();
    gemm_f16<1><<<dim3(4, 256), 256>>>(qzf_p, wbf_p, b_out, out);
}

// round 15
// speedup vs baseline: 2.1495x; 1.0196x over previous
#include <cuda_runtime.h>
#include <cuda_bf16.h>
#include <cuda_fp16.h>
#include <math.h>
#include <stdint.h>

#define MROWS (4 * 8192)          // 32768 rows total
#define DIMK  512
#define NQKV  1536

// ---------------- scratch (device globals; no allocation allowed) ----------
__device__ __half g_qf[MROWS * 512];        // elu(q)+1 fp16
__device__ __half g_kf[MROWS * 512];        // elu(k)+1 fp16
__device__ __half g_vf[MROWS * 512];        // v fp16
__device__ float g_kvpart[32 * 16 * 4160];  // per (bh,chunk): 64x64 kv + 64 ksum
__device__ float g_kv[32 * 4160];
__device__ float g_wt[NQKV * 512];          // w_qkv^T fp32 [n][k]

__device__ __half g_xf[MROWS * 512];        // x single fp16
__device__ __half g_wf[NQKV * 512];         // w^T single fp16
__device__ __half g_qzf[MROWS * 512];       // (q*z*2^15) single fp16
__device__ __half g_wbf[4 * 512 * 512];     // Wbig^T single fp16 [b][j][r]

#define QZ_SCALE 32768.0f
#define QZ_INV   (1.0f / 32768.0f)

// ---------------- helpers ---------------------------------------------------
__device__ __forceinline__ void mma16816h(float* c, const uint32_t* a, const uint32_t* b) {
    asm volatile(
        "mma.sync.aligned.m16n8k16.row.col.f32.f16.f16.f32 "
        "{%0,%1,%2,%3}, {%4,%5,%6,%7}, {%8,%9}, {%0,%1,%2,%3};"
        : "+f"(c[0]), "+f"(c[1]), "+f"(c[2]), "+f"(c[3])
        : "r"(a[0]), "r"(a[1]), "r"(a[2]), "r"(a[3]), "r"(b[0]), "r"(b[1]));
}
__device__ __forceinline__ void ldsm4(uint32_t* r, uint32_t a) {
    asm volatile("ldmatrix.sync.aligned.m8n8.x4.shared.b16 {%0,%1,%2,%3}, [%4];"
        : "=r"(r[0]), "=r"(r[1]), "=r"(r[2]), "=r"(r[3]) : "r"(a));
}
__device__ __forceinline__ uint32_t smem_u32(const void* p) {
    uint32_t a;
    asm("{ .reg .u64 t; cvta.to.shared.u64 t, %1; cvt.u32.u64 %0, t; }" : "=r"(a) : "l"(p));
    return a;
}
__device__ __forceinline__ void cp16(uint32_t s, const void* g) {
    asm volatile("cp.async.cg.shared.global [%0], [%1], 16;" :: "r"(s), "l"(g));
}
__device__ __forceinline__ float elu1(float x) {
    return x >= 0.f ? x + 1.f : __expf(x);
}

// ============================================================================
// W transpose: g_wt[n][k] = W[k][n]   (W: [512][1536])   [R5-verified]
// ============================================================================
__global__ void transpose_w(const float* __restrict__ W)
{
    __shared__ float t[32][33];
    const int bx = blockIdx.x * 32;   // n base
    const int by = blockIdx.y * 32;   // k base
    const int x = threadIdx.x;
    for (int yy = threadIdx.y; yy < 32; yy += 8)
        t[yy][x] = W[(size_t)(by + yy) * NQKV + bx + x];
    __syncthreads();
    for (int yy = threadIdx.y; yy < 32; yy += 8)
        g_wt[(size_t)(bx + yy) * 512 + by + x] = t[x][yy];
}

// ============================================================================
// conv_x_f16: X fp32 -> single fp16 (same index)  [R12-verified]
// ============================================================================
__global__ void conv_x_f16(const float* __restrict__ X)
{
    size_t i4 = (size_t)blockIdx.x * 256 + threadIdx.x;
    float4 v = ((const float4*)X)[i4];
    __half2* O = (__half2*)g_xf;
    O[i4 * 2]     = __floats2half2_rn(v.x, v.y);
    O[i4 * 2 + 1] = __floats2half2_rn(v.z, v.w);
}

// ============================================================================
// conv_w_f16: g_wt fp32 -> single fp16 (same index)  [R14-verified]
// ============================================================================
__global__ void conv_w_f16()
{
    size_t i = (size_t)blockIdx.x * 256 + threadIdx.x;
    g_wf[i] = __float2half_rn(g_wt[i]);
}

// ============================================================================
// z_split: fused compute_z + qz conversion; q now read as fp16.
// (dot/shfl structure R8/R13-verified)
// ============================================================================
__global__ __launch_bounds__(128) void z_split()
{
    const int row = blockIdx.x;            // 0..32767
    const int b = row >> 13;
    const int t = threadIdx.x;             // 0..127
    const int h = t >> 4;
    const int e = t * 4;
    const int d = e & 63;

    size_t o2 = ((size_t)row * 512 + e) >> 1;
    __half2 q01 = ((const __half2*)g_qf)[o2];
    __half2 q23 = ((const __half2*)g_qf)[o2 + 1];
    float qx = __half2float(__low2half(q01)),  qy = __half2float(__high2half(q01));
    float qz2 = __half2float(__low2half(q23)), qw = __half2float(__high2half(q23));

    const float* ks = g_kv + (size_t)(b * 8 + h) * 4160 + 4096 + d;
    float part = qx * ks[0] + qy * ks[1] + qz2 * ks[2] + qw * ks[3];
#pragma unroll
    for (int off = 8; off; off >>= 1)
        part += __shfl_xor_sync(0xFFFFFFFFu, part, off);
    const float zs = QZ_SCALE / (part + 1e-6f);

    __half2* O = (__half2*)g_qzf;
    O[o2]     = __floats2half2_rn(qx * zs, qy * zs);
    O[o2 + 1] = __floats2half2_rn(qz2 * zs, qw * zs);
}

// ============================================================================
// fp16 single-product GEMM [R14-verified skeleton]: C = A @ B.
// C tile 128x128, K=512 in 32 chunks of 16. XOR-swizzled 32B rows;
// chunk buffer = 2 arrays x 4096B = 8KB; 4 buffers = 32KB static smem;
// 4-stage cp.async pipeline.
// MODE 0: A=x, B=Wqkv^T -> q/k/v *fp16* with elu+1 on q,k
// MODE 1: A=qz*2^15, B=Wbig^T[b] -> Out = C*2^-15 + bias (fp32)
// ============================================================================
#define ABYTES 4096                    // one array: 128 rows x 32 B
#define BUF0B (2 * ABYTES)             // 8192 B per chunk buffer

template <int MODE>
__global__ __launch_bounds__(256, 2) void gemm_f16(
    const __half* __restrict__ Ag, const __half* __restrict__ Bg,
    const float* __restrict__ bias, float* __restrict__ Out)
{
    __shared__ __half smem[4 * BUF0B / 2];   // 32 KB

    const int tid = threadIdx.x;
    const int wid = tid >> 5, lane = tid & 31;
    const int g = lane >> 2, tig = lane & 3;
    const int m0 = blockIdx.y * 128;
    const int n0 = blockIdx.x * 128;
    const int wm = (wid & 1) * 64;
    const int wn = (wid >> 1) * 32;
    const int bb = m0 >> 13;          // batch (tiles never straddle batches)

    const __half* B = Bg + (MODE == 1 ? (size_t)bb * 262144 : 0);

    // fill mapping: thread t -> row = t>>1, k8-group j = t&1, swizzled slot
    const int frow = tid >> 1, fj = tid & 1;
    const int fslot = fj ^ ((frow >> 2) & 1);
    const uint32_t sOff = (uint32_t)(frow * 32 + fslot * 16);
    const __half* ga = Ag + (size_t)(m0 + frow) * 512 + fj * 8;
    const __half* gb = B  + (size_t)(n0 + frow) * 512 + fj * 8;

    const uint32_t sBase = smem_u32(smem);

    // ldmatrix per-lane offsets [R11-verified swizzle]
    const int ar = lane & 15, akh = lane >> 4;
    const uint32_t aoff =
        (uint32_t)((wm + ar) * 32 + ((akh ^ ((ar >> 2) & 1)) * 16));
    const int brl = ((lane >> 4) & 1) * 8 + (lane & 7);
    const int bkh = (lane >> 3) & 1;
    const uint32_t boff =
        (uint32_t)((wn + brl) * 32 + ((bkh ^ (((lane & 7) >> 2) & 1)) * 16));

    auto issue = [&](int k0, int bufI) {
        const uint32_t nb = sBase + (uint32_t)(bufI * BUF0B);
        cp16(nb + 0 * ABYTES + sOff, ga + k0);
        cp16(nb + 1 * ABYTES + sOff, gb + k0);
        asm volatile("cp.async.commit_group;" ::: "memory");
    };

    float acc[4][4][4];
#pragma unroll
    for (int i = 0; i < 4; i++)
#pragma unroll
        for (int j = 0; j < 4; j++)
#pragma unroll
            for (int t = 0; t < 4; t++) acc[i][j][t] = 0.f;

    // ---- prologue: chunks 0,1,2 into buffers 0,1,2 ----
    issue(0, 0);
    issue(16, 1);
    issue(32, 2);

    for (int kc = 0; kc < 32; kc++) {
        if (kc < 30) {
            asm volatile("cp.async.wait_group 2;" ::: "memory");
        } else if (kc == 30) {
            asm volatile("cp.async.wait_group 1;" ::: "memory");
        } else {
            asm volatile("cp.async.wait_group 0;" ::: "memory");
        }
        __syncthreads();   // chunk kc visible; all warps done with buf (kc+3)&3

        if (kc <= 28) issue((kc + 3) * 16, (kc + 3) & 3);

        const uint32_t cb = sBase + (uint32_t)((kc & 3) * BUF0B);
        const uint32_t aBase = cb + aoff;
        const uint32_t bBase = cb + ABYTES + boff;

        uint32_t a4[4][4];
#pragma unroll
        for (int mt = 0; mt < 4; mt++)
            ldsm4(a4[mt], aBase + (uint32_t)(mt * 512));
#pragma unroll
        for (int ntp = 0; ntp < 2; ntp++) {
            uint32_t b4[4];
            ldsm4(b4, bBase + (uint32_t)(ntp * 512));
#pragma unroll
            for (int half = 0; half < 2; half++) {
                const int nt = ntp * 2 + half;
                const uint32_t* bfrag = b4 + half * 2;
#pragma unroll
                for (int mt = 0; mt < 4; mt++)
                    mma16816h(acc[mt][nt], a4[mt], bfrag);
            }
        }
    }

    // -------- epilogue --------
    if (MODE == 0) {
        __half* dst = (n0 < 512) ? g_qf : (n0 < 1024 ? g_kf : g_vf);
        const bool act = (n0 < 1024);
        const int cb2 = (n0 & 511) + wn;
#pragma unroll
        for (int mt = 0; mt < 4; mt++) {
            int r0 = m0 + wm + mt * 16 + g;
#pragma unroll
            for (int nt = 0; nt < 4; nt++) {
                int c = cb2 + nt * 8 + tig * 2;
                float v0 = acc[mt][nt][0], v1 = acc[mt][nt][1];
                float v2 = acc[mt][nt][2], v3 = acc[mt][nt][3];
                if (act) { v0 = elu1(v0); v1 = elu1(v1); v2 = elu1(v2); v3 = elu1(v3); }
                *(__half2*)&dst[(size_t)r0 * 512 + c]       = __floats2half2_rn(v0, v1);
                *(__half2*)&dst[(size_t)(r0 + 8) * 512 + c] = __floats2half2_rn(v2, v3);
            }
        }
    } else {
        const int cb2 = n0 + wn;
#pragma unroll
        for (int mt = 0; mt < 4; mt++) {
            int r0 = m0 + wm + mt * 16 + g;
#pragma unroll
            for (int nt = 0; nt < 4; nt++) {
                int c = cb2 + nt * 8 + tig * 2;
                float b0 = bias[c], b1 = bias[c + 1];
                *(float2*)&Out[(size_t)r0 * 512 + c] =
                    make_float2(acc[mt][nt][0] * QZ_INV + b0,
                                acc[mt][nt][1] * QZ_INV + b1);
                *(float2*)&Out[(size_t)(r0 + 8) * 512 + c] =
                    make_float2(acc[mt][nt][2] * QZ_INV + b0,
                                acc[mt][nt][3] * QZ_INV + b1);
            }
        }
    }
}

// ============================================================================
// kv partial reduce (fp32 accumulation from fp16 inputs) [R1/R5-verified
// structure; only the global load format changed]
// ============================================================================
__global__ __launch_bounds__(256, 4) void kv_reduce()
{
    __shared__ float ks[8][64];
    __shared__ float vs[8][64];
    const int bh = blockIdx.x;
    const int b = bh >> 3, h = bh & 7;
    const int nbase = blockIdx.y * 512;
    const int tid = threadIdx.x;
    const int tx = tid & 15, ty = tid >> 4;

    float acc[4][4];
#pragma unroll
    for (int i = 0; i < 4; i++)
#pragma unroll
        for (int j = 0; j < 4; j++) acc[i][j] = 0.f;
    float ksacc[4] = {0.f, 0.f, 0.f, 0.f};

    const int lr = (tid & 127) >> 4;
    const int lc = tid & 15;
    const __half* src = (tid < 128) ? g_kf : g_vf;
    float* sdst = (tid < 128) ? &ks[lr][lc * 4] : &vs[lr][lc * 4];

    for (int r0 = 0; r0 < 512; r0 += 8) {
        int n = nbase + r0 + lr;
        uint2 raw = *(const uint2*)&src[((size_t)(b * 8192 + n)) * 512 + h * 64 + lc * 4];
        __half2 p0 = *(__half2*)&raw.x;
        __half2 p1 = *(__half2*)&raw.y;
        float4 val;
        val.x = __half2float(__low2half(p0));
        val.y = __half2float(__high2half(p0));
        val.z = __half2float(__low2half(p1));
        val.w = __half2float(__high2half(p1));
        *(float4*)sdst = val;
        __syncthreads();
#pragma unroll
        for (int r = 0; r < 8; r++) {
            float kf[4], vf[4];
            *(float4*)kf = *(float4*)&ks[r][tx * 4];
            *(float4*)vf = *(float4*)&vs[r][ty * 4];
#pragma unroll
            for (int i = 0; i < 4; i++)
#pragma unroll
                for (int j = 0; j < 4; j++) acc[i][j] += kf[i] * vf[j];
            if (ty == 0) {
#pragma unroll
                for (int i = 0; i < 4; i++) ksacc[i] += kf[i];
            }
        }
        __syncthreads();
    }

    const size_t base = (size_t)(bh * 16 + blockIdx.y) * 4160;
#pragma unroll
    for (int i = 0; i < 4; i++)
#pragma unroll
        for (int j = 0; j < 4; j++)
            g_kvpart[base + (tx * 4 + i) * 64 + ty * 4 + j] = acc[i][j];
    if (ty == 0) {
#pragma unroll
        for (int i = 0; i < 4; i++) g_kvpart[base + 4096 + tx * 4 + i] = ksacc[i];
    }
}

__global__ void kv_combine()
{
    const int bh = blockIdx.x;
    const int i0 = blockIdx.y * 260;
    const int iend = (i0 + 260 < 4160) ? i0 + 260 : 4160;
    for (int i = i0 + threadIdx.x; i < iend; i += 256) {
        float s = 0.f;
#pragma unroll
        for (int c = 0; c < 16; c++) s += g_kvpart[(size_t)(bh * 16 + c) * 4160 + i];
        g_kv[(size_t)bh * 4160 + i] = s;
    }
}

// ============================================================================
// Wbig^T single fp16: [b][j][r] = sum_m kv[b,h,d,m] * w_out[h*64+m][j]
// [R14-verified]
// ============================================================================
__global__ void make_wbig(const float* __restrict__ Wout)
{
    const int r = blockIdx.x;          // h*64+d
    const int b = blockIdx.y;
    const int h = r >> 6, d = r & 63;
    __shared__ float kvrow[64];
    if (threadIdx.x < 64)
        kvrow[threadIdx.x] = g_kv[(size_t)(b * 8 + h) * 4160 + d * 64 + threadIdx.x];
    __syncthreads();
    float acc[4] = {0.f, 0.f, 0.f, 0.f};
    for (int m = 0; m < 64; m++) {
        float kvv = kvrow[m];
        const float* wrow = Wout + (size_t)(h * 64 + m) * 512;
#pragma unroll
        for (int i = 0; i < 4; i++) acc[i] += kvv * wrow[threadIdx.x + i * 128];
    }
#pragma unroll
    for (int i = 0; i < 4; i++) {
        int j = threadIdx.x + i * 128;
        g_wbf[(size_t)b * 262144 + (size_t)j * 512 + r] = __float2half_rn(acc[i]);
    }
}

// ============================================================================
extern "C" void kernel_launch(void* const* d_in, const int* in_sizes, int n_in,
                              void* d_out, int out_size)
{
    const float* x     = (const float*)d_in[0];   // [4,8192,512]
    const float* w_qkv = (const float*)d_in[1];   // [512,1536]
    const float* w_out = (const float*)d_in[2];   // [512,512]
    const float* b_out = (const float*)d_in[3];   // [512]
    float* out = (float*)d_out;                   // [4,8192,512]

    __half *xf_p, *wf_p, *qzf_p, *wbf_p;
    cudaGetSymbolAddress((void**)&xf_p,  g_xf);
    cudaGetSymbolAddress((void**)&wf_p,  g_wf);
    cudaGetSymbolAddress((void**)&qzf_p, g_qzf);
    cudaGetSymbolAddress((void**)&wbf_p, g_wbf);

    transpose_w<<<dim3(48, 16), dim3(32, 8)>>>(w_qkv);
    conv_x_f16<<<16384, 256>>>(x);
    conv_w_f16<<<3072, 256>>>();
    gemm_f16<0><<<dim3(12, 256), 256>>>(xf_p, wf_p, nullptr, nullptr);
    kv_reduce<<<dim3(32, 16), 256>>>();
    kv_combine<<<dim3(32, 16), 256>>>();
    make_wbig<<<dim3(512, 4), 128>>>(w_out);
    z_split<<<32768, 128>>>();
    gemm_f16<1><<<dim3(4, 256), 256>>>(qzf_p, wbf_p, b_out, out);
}